// round 1
// baseline (speedup 1.0000x reference)
#include <cuda_runtime.h>

// Problem constants
#define RR   128      // msa rows
#define NN   512      // seq len
#define DIMC 128      // d_msa
#define HH   8        // heads
#define DHC  32       // dim_head
#define DPP  128      // d_pair
#define INNERC 256    // H*DH
#define RDC  4096     // R*DH fused contraction axis
#define MRN  65536    // R*N

// ---------------- scratch (device globals; no allocation allowed) -------------
__device__ __align__(16) float g_q   [HH * NN * RDC];  // weighted q~ : [h][n][r*32+d]
__device__ __align__(16) float g_k   [HH * NN * RDC];  // [h][n][r*32+d]
__device__ __align__(16) float g_v   [HH * NN * RDC];  // [h][n][r*32+d]
__device__ __align__(16) float g_o   [HH * NN * RDC];  // attn@V result
__device__ __align__(16) float g_ksw [MRN * DIMC];     // x @ Wk_sw + bk
__device__ __align__(16) float g_qsw [NN * DIMC];      // x[0] @ Wq_sw + bq
__device__ __align__(16) float g_wrow[NN * HH * RR];   // row weights (softmaxed in place)
__device__ __align__(16) float g_dots[HH * NN * NN];   // logits -> attn (in place)
__device__ __align__(16) float g_pbh [HH * NN * NN];   // pair bias per head

// =============================================================================
// q_sw = x[0] @ Wq_sw + bq_sw          (512 x 128, tiny)
// =============================================================================
__global__ void qsw_kernel(const float* __restrict__ x,
                           const float* __restrict__ Wq_sw,
                           const float* __restrict__ bq_sw) {
    int n = blockIdx.x;
    int c = threadIdx.x;
    __shared__ float xr[DIMC];
    xr[c] = x[(size_t)n * DIMC + c];   // x[r=0][n][c]
    __syncthreads();
    float acc = bq_sw[c];
#pragma unroll 8
    for (int k = 0; k < DIMC; k++) acc += xr[k] * Wq_sw[k * DIMC + c];
    g_qsw[n * DIMC + c] = acc;
}

// =============================================================================
// k_sw GEMM: g_ksw[m, c] = x[m,:] @ Wk_sw[:,c] + bk_sw[c]   (65536 x 128, K=128)
// 64x64 block tile, 16 K-step, 256 threads, 4x4 per thread.
// =============================================================================
__global__ void ksw_gemm_kernel(const float* __restrict__ x,
                                const float* __restrict__ Wk_sw,
                                const float* __restrict__ bk_sw) {
    __shared__ float As[16][64];
    __shared__ float Bs[16][64];
    const int tid = threadIdx.x;
    const int m0 = blockIdx.y * 64, c0 = blockIdx.x * 64;
    const int ty = tid >> 4, tx = tid & 15;
    const int lrow = tid >> 2, lk4 = (tid & 3) * 4;
    const int brow = tid >> 4, bc4 = (tid & 15) * 4;
    float acc[4][4] = {};
    for (int k0 = 0; k0 < 128; k0 += 16) {
        float4 av = *reinterpret_cast<const float4*>(&x[(size_t)(m0 + lrow) * 128 + k0 + lk4]);
        As[lk4 + 0][lrow] = av.x; As[lk4 + 1][lrow] = av.y;
        As[lk4 + 2][lrow] = av.z; As[lk4 + 3][lrow] = av.w;
        *reinterpret_cast<float4*>(&Bs[brow][bc4]) =
            *reinterpret_cast<const float4*>(&Wk_sw[(size_t)(k0 + brow) * 128 + c0 + bc4]);
        __syncthreads();
#pragma unroll
        for (int k = 0; k < 16; k++) {
            float4 a = *reinterpret_cast<const float4*>(&As[k][ty * 4]);
            float4 b = *reinterpret_cast<const float4*>(&Bs[k][tx * 4]);
            float ar[4] = {a.x, a.y, a.z, a.w};
            float br[4] = {b.x, b.y, b.z, b.w};
#pragma unroll
            for (int i = 0; i < 4; i++)
#pragma unroll
                for (int j = 0; j < 4; j++) acc[i][j] += ar[i] * br[j];
        }
        __syncthreads();
    }
#pragma unroll
    for (int i = 0; i < 4; i++) {
        int m = m0 + ty * 4 + i;
#pragma unroll
        for (int j = 0; j < 4; j++) {
            int c = c0 + tx * 4 + j;
            g_ksw[(size_t)m * 128 + c] = acc[i][j] + bk_sw[c];
        }
    }
}

// =============================================================================
// sw[n,h,r] = sum_{d<16} ksw[r,n,h*16+d] * qsw[n,h*16+d] * 0.25
// one block per (r,n); 128 threads; 16-lane shuffle reduce
// =============================================================================
__global__ void sw_reduce_kernel() {
    int m = blockIdx.x;            // r*512 + n
    int r = m >> 9, n = m & 511;
    int c = threadIdx.x;
    float prod = g_ksw[(size_t)m * 128 + c] * g_qsw[n * 128 + c];
#pragma unroll
    for (int o = 8; o; o >>= 1) prod += __shfl_down_sync(0xffffffffu, prod, o, 16);
    if ((c & 15) == 0) {
        int h = c >> 4;
        g_wrow[(n * HH + h) * RR + r] = prod * 0.25f;   // / sqrt(16 + 1e-8)
    }
}

// =============================================================================
// softmax over r (128 values) per (n,h) row; in place on g_wrow
// =============================================================================
__global__ void wrow_softmax_kernel() {
    int row = blockIdx.x;          // n*8 + h
    int t = threadIdx.x;
    float v = g_wrow[(size_t)row * 128 + t];
    __shared__ float sm[128];
    sm[t] = v; __syncthreads();
#pragma unroll
    for (int s = 64; s > 0; s >>= 1) { if (t < s) sm[t] = fmaxf(sm[t], sm[t + s]); __syncthreads(); }
    float mx = sm[0]; __syncthreads();
    float e = expf(v - mx);
    sm[t] = e; __syncthreads();
#pragma unroll
    for (int s = 64; s > 0; s >>= 1) { if (t < s) sm[t] += sm[t + s]; __syncthreads(); }
    g_wrow[(size_t)row * 128 + t] = e / sm[0];
}

// =============================================================================
// QKV GEMM: [x @ Wq | x @ Wkv]  (65536 x 768, K=128)
// epilogue scatters to [h][n][r*32+d] layout; q gets w_row weighting fused.
// =============================================================================
__global__ void qkv_gemm_kernel(const float* __restrict__ x,
                                const float* __restrict__ Wq,
                                const float* __restrict__ Wkv) {
    __shared__ float As[16][64];
    __shared__ float Bs[16][64];
    const int tid = threadIdx.x;
    const int m0 = blockIdx.y * 64, c0 = blockIdx.x * 64;
    const int ty = tid >> 4, tx = tid & 15;
    const int lrow = tid >> 2, lk4 = (tid & 3) * 4;
    const int brow = tid >> 4, bc4 = (tid & 15) * 4;

    const float* B; int ldb, cb, mode;
    if (c0 < 256)      { B = Wq;  ldb = 256; cb = c0;       mode = 0; }
    else if (c0 < 512) { B = Wkv; ldb = 512; cb = c0 - 256; mode = 1; }
    else               { B = Wkv; ldb = 512; cb = c0 - 256; mode = 2; }

    float acc[4][4] = {};
    for (int k0 = 0; k0 < 128; k0 += 16) {
        float4 av = *reinterpret_cast<const float4*>(&x[(size_t)(m0 + lrow) * 128 + k0 + lk4]);
        As[lk4 + 0][lrow] = av.x; As[lk4 + 1][lrow] = av.y;
        As[lk4 + 2][lrow] = av.z; As[lk4 + 3][lrow] = av.w;
        *reinterpret_cast<float4*>(&Bs[brow][bc4]) =
            *reinterpret_cast<const float4*>(&B[(size_t)(k0 + brow) * ldb + cb + bc4]);
        __syncthreads();
#pragma unroll
        for (int k = 0; k < 16; k++) {
            float4 a = *reinterpret_cast<const float4*>(&As[k][ty * 4]);
            float4 b = *reinterpret_cast<const float4*>(&Bs[k][tx * 4]);
            float ar[4] = {a.x, a.y, a.z, a.w};
            float br[4] = {b.x, b.y, b.z, b.w};
#pragma unroll
            for (int i = 0; i < 4; i++)
#pragma unroll
                for (int j = 0; j < 4; j++) acc[i][j] += ar[i] * br[j];
        }
        __syncthreads();
    }
#pragma unroll
    for (int i = 0; i < 4; i++) {
        int m = m0 + ty * 4 + i;
        int r = m >> 9, n = m & 511;
#pragma unroll
        for (int j = 0; j < 4; j++) {
            int c = c0 + tx * 4 + j;
            float val = acc[i][j];
            if (mode == 0) {
                int h = c >> 5, d = c & 31;
                val *= g_wrow[(n * HH + h) * RR + r];
                g_q[(((size_t)h << 9) + n) * RDC + (r << 5) + d] = val;
            } else if (mode == 1) {
                int cc = c - 256; int h = cc >> 5, d = cc & 31;
                g_k[(((size_t)h << 9) + n) * RDC + (r << 5) + d] = val;
            } else {
                int cc = c - 512; int h = cc >> 5, d = cc & 31;
                g_v[(((size_t)h << 9) + n) * RDC + (r << 5) + d] = val;
            }
        }
    }
}

// =============================================================================
// pair bias: LayerNorm over DP=128, project to H heads.  One warp per (i,j).
// =============================================================================
__global__ void pbh_kernel(const float* __restrict__ pair_bias,
                           const float* __restrict__ ln_g,
                           const float* __restrict__ ln_b,
                           const float* __restrict__ Wpair) {
    int warp = threadIdx.x >> 5, lane = threadIdx.x & 31;
    int idx = blockIdx.x * 8 + warp;      // i*512 + j
    int i = idx >> 9, j = idx & 511;
    float4 v = *reinterpret_cast<const float4*>(&pair_bias[(size_t)idx * 128 + lane * 4]);
    float s  = v.x + v.y + v.z + v.w;
    float sq = v.x * v.x + v.y * v.y + v.z * v.z + v.w * v.w;
#pragma unroll
    for (int o = 16; o; o >>= 1) {
        s  += __shfl_xor_sync(0xffffffffu, s, o);
        sq += __shfl_xor_sync(0xffffffffu, sq, o);
    }
    float mean = s * (1.0f / 128.0f);
    float var  = sq * (1.0f / 128.0f) - mean * mean;
    float rstd = rsqrtf(var + 1e-5f);
    float vv[4] = {v.x, v.y, v.z, v.w};
    float ph[8] = {};
#pragma unroll
    for (int e = 0; e < 4; e++) {
        int p = lane * 4 + e;
        float nz = (vv[e] - mean) * rstd * ln_g[p] + ln_b[p];
#pragma unroll
        for (int h = 0; h < 8; h++) ph[h] += nz * Wpair[p * 8 + h];
    }
#pragma unroll
    for (int h = 0; h < 8; h++)
#pragma unroll
        for (int o = 16; o; o >>= 1) ph[h] += __shfl_xor_sync(0xffffffffu, ph[h], o);
    if (lane == 0) {
#pragma unroll
        for (int h = 0; h < 8; h++)
            g_pbh[(((size_t)h << 9) + i) * NN + j] = ph[h];
    }
}

// =============================================================================
// dots GEMM (NT): per head, C[i,j] = sum_t Q~[i,t] K[j,t];  K dim = 4096.
// epilogue: *scale + pair bias.
// =============================================================================
__global__ void dots_gemm_kernel() {
    const int h = blockIdx.z;
    const float* A  = g_q + ((size_t)h << 21);   // 512*4096
    const float* Bm = g_k + ((size_t)h << 21);
    __shared__ float As[16][64];
    __shared__ float Bs[16][64];
    const int tid = threadIdx.x;
    const int i0 = blockIdx.y * 64, j0 = blockIdx.x * 64;
    const int ty = tid >> 4, tx = tid & 15;
    const int lrow = tid >> 2, lk4 = (tid & 3) * 4;
    float acc[4][4] = {};
    for (int k0 = 0; k0 < 4096; k0 += 16) {
        float4 av = *reinterpret_cast<const float4*>(&A [(size_t)(i0 + lrow) * RDC + k0 + lk4]);
        float4 bv = *reinterpret_cast<const float4*>(&Bm[(size_t)(j0 + lrow) * RDC + k0 + lk4]);
        As[lk4 + 0][lrow] = av.x; As[lk4 + 1][lrow] = av.y;
        As[lk4 + 2][lrow] = av.z; As[lk4 + 3][lrow] = av.w;
        Bs[lk4 + 0][lrow] = bv.x; Bs[lk4 + 1][lrow] = bv.y;
        Bs[lk4 + 2][lrow] = bv.z; Bs[lk4 + 3][lrow] = bv.w;
        __syncthreads();
#pragma unroll
        for (int k = 0; k < 16; k++) {
            float4 a = *reinterpret_cast<const float4*>(&As[k][ty * 4]);
            float4 b = *reinterpret_cast<const float4*>(&Bs[k][tx * 4]);
            float ar[4] = {a.x, a.y, a.z, a.w};
            float br[4] = {b.x, b.y, b.z, b.w};
#pragma unroll
            for (int i = 0; i < 4; i++)
#pragma unroll
                for (int j = 0; j < 4; j++) acc[i][j] += ar[i] * br[j];
        }
        __syncthreads();
    }
    const float scale = 0.17677669529663687f;    // 1/sqrt(32)
#pragma unroll
    for (int i = 0; i < 4; i++) {
        int ii = i0 + ty * 4 + i;
#pragma unroll
        for (int j = 0; j < 4; j++) {
            int jj = j0 + tx * 4 + j;
            size_t off = (((size_t)h << 9) + ii) * NN + jj;
            g_dots[off] = acc[i][j] * scale + g_pbh[off];
        }
    }
}

// =============================================================================
// softmax over j (512 values) per (h,i); in place on g_dots
// =============================================================================
__global__ void attn_softmax_kernel() {
    size_t row = blockIdx.x;       // h*512 + i
    int t = threadIdx.x;
    float* p = g_dots + row * NN;
    float v0 = p[t], v1 = p[t + 256];
    __shared__ float sm[256];
    sm[t] = fmaxf(v0, v1); __syncthreads();
#pragma unroll
    for (int s = 128; s > 0; s >>= 1) { if (t < s) sm[t] = fmaxf(sm[t], sm[t + s]); __syncthreads(); }
    float mx = sm[0]; __syncthreads();
    float e0 = expf(v0 - mx), e1 = expf(v1 - mx);
    sm[t] = e0 + e1; __syncthreads();
#pragma unroll
    for (int s = 128; s > 0; s >>= 1) { if (t < s) sm[t] += sm[t + s]; __syncthreads(); }
    float inv = 1.0f / sm[0];
    p[t] = e0 * inv; p[t + 256] = e1 * inv;
}

// =============================================================================
// O GEMM (NN): per head, O[i,t] = sum_j attn[i,j] V[j,t];  512x4096, K=512
// =============================================================================
__global__ void o_gemm_kernel() {
    const int h = blockIdx.z;
    const float* A  = g_dots + ((size_t)h << 18);  // 512*512
    const float* Bm = g_v    + ((size_t)h << 21);  // 512*4096
    __shared__ float As[16][64];
    __shared__ float Bs[16][64];
    const int tid = threadIdx.x;
    const int t0 = blockIdx.x * 64, i0 = blockIdx.y * 64;
    const int ty = tid >> 4, tx = tid & 15;
    const int lrow = tid >> 2, lk4 = (tid & 3) * 4;
    const int brow = tid >> 4, bc4 = (tid & 15) * 4;
    float acc[4][4] = {};
    for (int k0 = 0; k0 < 512; k0 += 16) {
        float4 av = *reinterpret_cast<const float4*>(&A[(size_t)(i0 + lrow) * NN + k0 + lk4]);
        As[lk4 + 0][lrow] = av.x; As[lk4 + 1][lrow] = av.y;
        As[lk4 + 2][lrow] = av.z; As[lk4 + 3][lrow] = av.w;
        *reinterpret_cast<float4*>(&Bs[brow][bc4]) =
            *reinterpret_cast<const float4*>(&Bm[(size_t)(k0 + brow) * RDC + t0 + bc4]);
        __syncthreads();
#pragma unroll
        for (int k = 0; k < 16; k++) {
            float4 a = *reinterpret_cast<const float4*>(&As[k][ty * 4]);
            float4 b = *reinterpret_cast<const float4*>(&Bs[k][tx * 4]);
            float ar[4] = {a.x, a.y, a.z, a.w};
            float br[4] = {b.x, b.y, b.z, b.w};
#pragma unroll
            for (int i = 0; i < 4; i++)
#pragma unroll
                for (int j = 0; j < 4; j++) acc[i][j] += ar[i] * br[j];
        }
        __syncthreads();
    }
#pragma unroll
    for (int i = 0; i < 4; i++) {
        int ii = i0 + ty * 4 + i;
#pragma unroll
        for (int j = 0; j < 4; j++) {
            int tt = t0 + tx * 4 + j;
            g_o[(((size_t)h << 9) + ii) * RDC + tt] = acc[i][j];
        }
    }
}

// =============================================================================
// final GEMM: out[(r,n), c] = sum_{h,d} O[h][n][r*32+d] * Wout[h*32+d, c] + b_out
// A tile gathered from g_o layout.  M=65536, K=256, Nc=128.
// =============================================================================
__global__ void out_gemm_kernel(const float* __restrict__ Wout,
                                const float* __restrict__ b_out,
                                float* __restrict__ out) {
    __shared__ float As[16][64];
    __shared__ float Bs[16][64];
    const int tid = threadIdx.x;
    const int m0 = blockIdx.y * 64, c0 = blockIdx.x * 64;
    const int ty = tid >> 4, tx = tid & 15;
    const int lrow = tid >> 2, lk4 = (tid & 3) * 4;
    const int brow = tid >> 4, bc4 = (tid & 15) * 4;
    float acc[4][4] = {};
    for (int k0 = 0; k0 < 256; k0 += 16) {
        int m = m0 + lrow;
        int r = m >> 9, n = m & 511;
        int kk = k0 + lk4;
        int h = kk >> 5, dd = kk & 31;
        float4 av = *reinterpret_cast<const float4*>(
            &g_o[(((size_t)h << 9) + n) * RDC + (r << 5) + dd]);
        As[lk4 + 0][lrow] = av.x; As[lk4 + 1][lrow] = av.y;
        As[lk4 + 2][lrow] = av.z; As[lk4 + 3][lrow] = av.w;
        *reinterpret_cast<float4*>(&Bs[brow][bc4]) =
            *reinterpret_cast<const float4*>(&Wout[(size_t)(k0 + brow) * 128 + c0 + bc4]);
        __syncthreads();
#pragma unroll
        for (int k = 0; k < 16; k++) {
            float4 a = *reinterpret_cast<const float4*>(&As[k][ty * 4]);
            float4 b = *reinterpret_cast<const float4*>(&Bs[k][tx * 4]);
            float ar[4] = {a.x, a.y, a.z, a.w};
            float br[4] = {b.x, b.y, b.z, b.w};
#pragma unroll
            for (int i = 0; i < 4; i++)
#pragma unroll
                for (int j = 0; j < 4; j++) acc[i][j] += ar[i] * br[j];
        }
        __syncthreads();
    }
#pragma unroll
    for (int i = 0; i < 4; i++) {
        int m = m0 + ty * 4 + i;
#pragma unroll
        for (int j = 0; j < 4; j++) {
            int c = c0 + tx * 4 + j;
            out[(size_t)m * 128 + c] = acc[i][j] + b_out[c];
        }
    }
}

// =============================================================================
extern "C" void kernel_launch(void* const* d_in, const int* in_sizes, int n_in,
                              void* d_out, int out_size) {
    (void)in_sizes; (void)n_in; (void)out_size;
    const float* x         = (const float*)d_in[0];
    const float* pair_bias = (const float*)d_in[1];
    const float* Wq        = (const float*)d_in[2];
    const float* Wkv       = (const float*)d_in[3];
    const float* Wout      = (const float*)d_in[4];
    const float* b_out     = (const float*)d_in[5];
    const float* ln_g      = (const float*)d_in[6];
    const float* ln_b      = (const float*)d_in[7];
    const float* Wpair     = (const float*)d_in[8];
    const float* Wq_sw     = (const float*)d_in[9];
    const float* bq_sw     = (const float*)d_in[10];
    const float* Wk_sw     = (const float*)d_in[11];
    const float* bk_sw     = (const float*)d_in[12];
    float* out = (float*)d_out;

    qsw_kernel        <<<NN, 128>>>(x, Wq_sw, bq_sw);
    ksw_gemm_kernel   <<<dim3(2, 1024), 256>>>(x, Wk_sw, bk_sw);
    sw_reduce_kernel  <<<MRN, 128>>>();
    wrow_softmax_kernel<<<NN * HH, 128>>>();
    qkv_gemm_kernel   <<<dim3(12, 1024), 256>>>(x, Wq, Wkv);
    pbh_kernel        <<<NN * NN / 8, 256>>>(pair_bias, ln_g, ln_b, Wpair);
    dots_gemm_kernel  <<<dim3(8, 8, 8), 256>>>();
    attn_softmax_kernel<<<HH * NN, 256>>>();
    o_gemm_kernel     <<<dim3(64, 8, 8), 256>>>();
    out_gemm_kernel   <<<dim3(2, 1024), 256>>>(Wout, b_out, out);
}

// round 2
// speedup vs baseline: 1.5827x; 1.5827x over previous
#include <cuda_runtime.h>
#include <cstdint>

// Problem constants
#define RR   128
#define NN   512
#define DIMC 128
#define HH   8
#define DHC  32
#define DPP  128
#define INNERC 256
#define RDC  4096      // R*DH fused contraction axis
#define MRN  65536     // R*N

// ---------------- scratch (device globals) ------------------------------------
__device__ __align__(16) float g_q   [HH * NN * RDC];
__device__ __align__(16) float g_k   [HH * NN * RDC];
__device__ __align__(16) float g_v   [HH * NN * RDC];
__device__ __align__(16) float g_o   [HH * NN * RDC];
__device__ __align__(16) float g_ksw [MRN * DIMC];
__device__ __align__(16) float g_qsw [NN * DIMC];
__device__ __align__(16) float g_wrow[NN * HH * RR];
__device__ __align__(16) float g_dots[HH * NN * NN];
__device__ __align__(16) float g_pbh [HH * NN * NN];

// ---------------- tf32 helpers -------------------------------------------------
__device__ __forceinline__ float tf32r(float x) {
    uint32_t u;
    asm("cvt.rna.tf32.f32 %0, %1;" : "=r"(u) : "f"(x));
    return __uint_as_float(u);
}

__device__ __forceinline__ void mma8(float* c, const float* a, const float* b) {
    asm volatile(
        "mma.sync.aligned.m16n8k8.row.col.f32.tf32.tf32.f32 "
        "{%0,%1,%2,%3},{%4,%5,%6,%7},{%8,%9},{%0,%1,%2,%3};\n"
        : "+f"(c[0]), "+f"(c[1]), "+f"(c[2]), "+f"(c[3])
        : "r"(__float_as_uint(a[0])), "r"(__float_as_uint(a[1])),
          "r"(__float_as_uint(a[2])), "r"(__float_as_uint(a[3])),
          "r"(__float_as_uint(b[0])), "r"(__float_as_uint(b[1])));
}

// NT stage: tile [BM rows][32 k] from row-major src (k contiguous) -> As[m][36]
template<int BM, int NTHREADS>
__device__ __forceinline__ void load_nt(float (*As)[36], const float* __restrict__ src,
                                        int ld, int row0, int k0, int t) {
#pragma unroll
    for (int i = 0; i < BM * 8 / NTHREADS; i++) {
        int m  = (t >> 3) + i * (NTHREADS / 8);
        int kq = (t & 7) * 4;
        float4 v = *reinterpret_cast<const float4*>(src + (size_t)(row0 + m) * ld + k0 + kq);
        As[m][kq + 0] = tf32r(v.x); As[m][kq + 1] = tf32r(v.y);
        As[m][kq + 2] = tf32r(v.z); As[m][kq + 3] = tf32r(v.w);
    }
}

// NN stage: tile [32 k][BN cols] from row-major src (n contiguous) -> Bs[k][136]
template<int BN, int NTHREADS>
__device__ __forceinline__ void load_nn(float (*Bs)[136], const float* __restrict__ src,
                                        int ld, int k0, int col0, int t) {
#pragma unroll
    for (int i = 0; i < 32 * BN / 4 / NTHREADS; i++) {
        int k  = t / (BN / 4) + i * (NTHREADS / (BN / 4));
        int n4 = (t % (BN / 4)) * 4;
        float4 v = *reinterpret_cast<const float4*>(src + (size_t)(k0 + k) * ld + col0 + n4);
        Bs[k][n4 + 0] = tf32r(v.x); Bs[k][n4 + 1] = tf32r(v.y);
        Bs[k][n4 + 2] = tf32r(v.z); Bs[k][n4 + 3] = tf32r(v.w);
    }
}

// warp compute over one 32-deep k tile.  A: As[m][36].  B: NT -> [n][36], NN -> [k][136]
template<int MT, int NTILES, bool BNT>
__device__ __forceinline__ void compute_tile(const float (*As)[36], const float* BsRaw,
                                             float acc[MT][NTILES][4],
                                             int wm0, int wn0, int lane) {
    const int grp = lane >> 2, tid4 = lane & 3;
    const float (*BsT)[36]  = reinterpret_cast<const float (*)[36]>(BsRaw);
    const float (*BsN)[136] = reinterpret_cast<const float (*)[136]>(BsRaw);
#pragma unroll
    for (int kk = 0; kk < 32; kk += 8) {
        float a[MT][4];
#pragma unroll
        for (int mt = 0; mt < MT; mt++) {
            int mb = wm0 + mt * 16 + grp;
            a[mt][0] = As[mb][kk + tid4];
            a[mt][1] = As[mb + 8][kk + tid4];
            a[mt][2] = As[mb][kk + tid4 + 4];
            a[mt][3] = As[mb + 8][kk + tid4 + 4];
        }
        float b[NTILES][2];
#pragma unroll
        for (int nt = 0; nt < NTILES; nt++) {
            int nb = wn0 + nt * 8 + grp;
            if (BNT) {
                b[nt][0] = BsT[nb][kk + tid4];
                b[nt][1] = BsT[nb][kk + tid4 + 4];
            } else {
                b[nt][0] = BsN[kk + tid4][nb];
                b[nt][1] = BsN[kk + tid4 + 4][nb];
            }
        }
#pragma unroll
        for (int mt = 0; mt < MT; mt++)
#pragma unroll
            for (int nt = 0; nt < NTILES; nt++) mma8(acc[mt][nt], a[mt], b[nt]);
    }
}

// =============================================================================
// q_sw = x[0] @ Wq_sw + bq_sw      (tiny, fp32)
// =============================================================================
__global__ void qsw_kernel(const float* __restrict__ x,
                           const float* __restrict__ Wq_sw,
                           const float* __restrict__ bq_sw) {
    int n = blockIdx.x, c = threadIdx.x;
    __shared__ float xr[DIMC];
    xr[c] = x[(size_t)n * DIMC + c];
    __syncthreads();
    float acc = bq_sw[c];
#pragma unroll 8
    for (int k = 0; k < DIMC; k++) acc += xr[k] * Wq_sw[k * DIMC + c];
    g_qsw[n * DIMC + c] = acc;
}

// =============================================================================
// ksw GEMM (tensor core): 65536 x 128, K=128
// =============================================================================
__global__ __launch_bounds__(256) void ksw_gemm_tc(const float* __restrict__ x,
                                                   const float* __restrict__ Wk_sw,
                                                   const float* __restrict__ bk_sw) {
    __shared__ float As[128][36];
    __shared__ float Bs[32][136];
    const int t = threadIdx.x, lane = t & 31, warp = t >> 5;
    const int m0 = blockIdx.y * 128;
    const int wm0 = (warp >> 2) * 64, wn0 = (warp & 3) * 32;
    float acc[4][4][4] = {};
    for (int k0 = 0; k0 < 128; k0 += 32) {
        load_nt<128, 256>(As, x, 128, m0, k0, t);
        load_nn<128, 256>(Bs, Wk_sw, 128, k0, 0, t);
        __syncthreads();
        compute_tile<4, 4, false>(As, &Bs[0][0], acc, wm0, wn0, lane);
        __syncthreads();
    }
    const int grp = lane >> 2, tid4 = lane & 3;
#pragma unroll
    for (int mt = 0; mt < 4; mt++)
#pragma unroll
        for (int nt = 0; nt < 4; nt++)
#pragma unroll
            for (int f = 0; f < 4; f++) {
                int m = m0 + wm0 + mt * 16 + grp + ((f >= 2) ? 8 : 0);
                int c = wn0 + nt * 8 + tid4 * 2 + (f & 1);
                g_ksw[(size_t)m * 128 + c] = acc[mt][nt][f] + bk_sw[c];
            }
}

// =============================================================================
// sw reduce + row softmax (unchanged, fp32)
// =============================================================================
__global__ void sw_reduce_kernel() {
    int m = blockIdx.x;
    int r = m >> 9, n = m & 511;
    int c = threadIdx.x;
    float prod = g_ksw[(size_t)m * 128 + c] * g_qsw[n * 128 + c];
#pragma unroll
    for (int o = 8; o; o >>= 1) prod += __shfl_down_sync(0xffffffffu, prod, o, 16);
    if ((c & 15) == 0) g_wrow[(n * HH + (c >> 4)) * RR + r] = prod * 0.25f;
}

__global__ void wrow_softmax_kernel() {
    int row = blockIdx.x, t = threadIdx.x;
    float v = g_wrow[(size_t)row * 128 + t];
    __shared__ float sm[128];
    sm[t] = v; __syncthreads();
#pragma unroll
    for (int s = 64; s > 0; s >>= 1) { if (t < s) sm[t] = fmaxf(sm[t], sm[t + s]); __syncthreads(); }
    float mx = sm[0]; __syncthreads();
    float e = expf(v - mx);
    sm[t] = e; __syncthreads();
#pragma unroll
    for (int s = 64; s > 0; s >>= 1) { if (t < s) sm[t] += sm[t + s]; __syncthreads(); }
    g_wrow[(size_t)row * 128 + t] = e / sm[0];
}

// =============================================================================
// QKV GEMM (tensor core): 65536 x 768, K=128; epilogue scatter + w_row on q
// =============================================================================
__global__ __launch_bounds__(256) void qkv_gemm_tc(const float* __restrict__ x,
                                                   const float* __restrict__ Wq,
                                                   const float* __restrict__ Wkv) {
    __shared__ float As[128][36];
    __shared__ float Bs[32][136];
    const int t = threadIdx.x, lane = t & 31, warp = t >> 5;
    const int m0 = blockIdx.y * 128, c0 = blockIdx.x * 128;
    const int wm0 = (warp >> 2) * 64, wn0 = (warp & 3) * 32;
    const float* B; int ldB, cb;
    if (c0 < 256) { B = Wq;  ldB = 256; cb = c0; }
    else          { B = Wkv; ldB = 512; cb = c0 - 256; }
    float acc[4][4][4] = {};
    for (int k0 = 0; k0 < 128; k0 += 32) {
        load_nt<128, 256>(As, x, 128, m0, k0, t);
        load_nn<128, 256>(Bs, B, ldB, k0, cb, t);
        __syncthreads();
        compute_tile<4, 4, false>(As, &Bs[0][0], acc, wm0, wn0, lane);
        __syncthreads();
    }
    const int grp = lane >> 2, tid4 = lane & 3;
#pragma unroll
    for (int mt = 0; mt < 4; mt++)
#pragma unroll
        for (int nt = 0; nt < 4; nt++)
#pragma unroll
            for (int f = 0; f < 4; f++) {
                int m = m0 + wm0 + mt * 16 + grp + ((f >= 2) ? 8 : 0);
                int c = c0 + wn0 + nt * 8 + tid4 * 2 + (f & 1);
                int r = m >> 9, n = m & 511;
                float val = acc[mt][nt][f];
                if (c < 256) {
                    int h = c >> 5, d = c & 31;
                    val *= g_wrow[(n * HH + h) * RR + r];
                    g_q[(((size_t)h << 9) + n) * RDC + (r << 5) + d] = val;
                } else if (c < 512) {
                    int cc = c - 256, h = cc >> 5, d = cc & 31;
                    g_k[(((size_t)h << 9) + n) * RDC + (r << 5) + d] = val;
                } else {
                    int cc = c - 512, h = cc >> 5, d = cc & 31;
                    g_v[(((size_t)h << 9) + n) * RDC + (r << 5) + d] = val;
                }
            }
}

// =============================================================================
// pair bias LN + head projection (unchanged)
// =============================================================================
__global__ void pbh_kernel(const float* __restrict__ pair_bias,
                           const float* __restrict__ ln_g,
                           const float* __restrict__ ln_b,
                           const float* __restrict__ Wpair) {
    int warp = threadIdx.x >> 5, lane = threadIdx.x & 31;
    int idx = blockIdx.x * 8 + warp;
    int i = idx >> 9, j = idx & 511;
    float4 v = *reinterpret_cast<const float4*>(&pair_bias[(size_t)idx * 128 + lane * 4]);
    float s  = v.x + v.y + v.z + v.w;
    float sq = v.x * v.x + v.y * v.y + v.z * v.z + v.w * v.w;
#pragma unroll
    for (int o = 16; o; o >>= 1) {
        s  += __shfl_xor_sync(0xffffffffu, s, o);
        sq += __shfl_xor_sync(0xffffffffu, sq, o);
    }
    float mean = s * (1.0f / 128.0f);
    float var  = sq * (1.0f / 128.0f) - mean * mean;
    float rstd = rsqrtf(var + 1e-5f);
    float vv[4] = {v.x, v.y, v.z, v.w};
    float ph[8] = {};
#pragma unroll
    for (int e = 0; e < 4; e++) {
        int p = lane * 4 + e;
        float nz = (vv[e] - mean) * rstd * ln_g[p] + ln_b[p];
#pragma unroll
        for (int h = 0; h < 8; h++) ph[h] += nz * Wpair[p * 8 + h];
    }
#pragma unroll
    for (int h = 0; h < 8; h++)
#pragma unroll
        for (int o = 16; o; o >>= 1) ph[h] += __shfl_xor_sync(0xffffffffu, ph[h], o);
    if (lane == 0) {
#pragma unroll
        for (int h = 0; h < 8; h++)
            g_pbh[(((size_t)h << 9) + i) * NN + j] = ph[h];
    }
}

// =============================================================================
// dots GEMM (tensor core, NT): per head 512x512, K=4096.  64x64 tiles, 4 warps.
// =============================================================================
__global__ __launch_bounds__(128) void dots_gemm_tc() {
    const int h = blockIdx.z;
    const float* A  = g_q + ((size_t)h << 21);
    const float* Bm = g_k + ((size_t)h << 21);
    __shared__ float As[64][36];
    __shared__ float Bs[64][36];
    const int t = threadIdx.x, lane = t & 31, warp = t >> 5;
    const int i0 = blockIdx.y * 64, j0 = blockIdx.x * 64;
    const int wm0 = (warp >> 1) * 32, wn0 = (warp & 1) * 32;
    float acc[2][4][4] = {};
    for (int k0 = 0; k0 < 4096; k0 += 32) {
        load_nt<64, 128>(As, A,  RDC, i0, k0, t);
        load_nt<64, 128>(Bs, Bm, RDC, j0, k0, t);
        __syncthreads();
        compute_tile<2, 4, true>(As, &Bs[0][0], acc, wm0, wn0, lane);
        __syncthreads();
    }
    const float scale = 0.17677669529663687f;
    const int grp = lane >> 2, tid4 = lane & 3;
#pragma unroll
    for (int mt = 0; mt < 2; mt++)
#pragma unroll
        for (int nt = 0; nt < 4; nt++)
#pragma unroll
            for (int f = 0; f < 4; f++) {
                int ii = i0 + wm0 + mt * 16 + grp + ((f >= 2) ? 8 : 0);
                int jj = j0 + wn0 + nt * 8 + tid4 * 2 + (f & 1);
                size_t off = (((size_t)h << 9) + ii) * NN + jj;
                g_dots[off] = acc[mt][nt][f] * scale + g_pbh[off];
            }
}

// =============================================================================
// attention softmax over j (512) per (h,i)
// =============================================================================
__global__ void attn_softmax_kernel() {
    size_t row = blockIdx.x;
    int t = threadIdx.x;
    float* p = g_dots + row * NN;
    float v0 = p[t], v1 = p[t + 256];
    __shared__ float sm[256];
    sm[t] = fmaxf(v0, v1); __syncthreads();
#pragma unroll
    for (int s = 128; s > 0; s >>= 1) { if (t < s) sm[t] = fmaxf(sm[t], sm[t + s]); __syncthreads(); }
    float mx = sm[0]; __syncthreads();
    float e0 = expf(v0 - mx), e1 = expf(v1 - mx);
    sm[t] = e0 + e1; __syncthreads();
#pragma unroll
    for (int s = 128; s > 0; s >>= 1) { if (t < s) sm[t] += sm[t + s]; __syncthreads(); }
    float inv = 1.0f / sm[0];
    p[t] = e0 * inv; p[t + 256] = e1 * inv;
}

// =============================================================================
// O GEMM (tensor core, NN): per head 512 x 4096, K=512
// =============================================================================
__global__ __launch_bounds__(256) void o_gemm_tc() {
    const int h = blockIdx.z;
    const float* A  = g_dots + ((size_t)h << 18);
    const float* Bm = g_v    + ((size_t)h << 21);
    __shared__ float As[128][36];
    __shared__ float Bs[32][136];
    const int t = threadIdx.x, lane = t & 31, warp = t >> 5;
    const int i0 = blockIdx.y * 128, t0 = blockIdx.x * 128;
    const int wm0 = (warp >> 2) * 64, wn0 = (warp & 3) * 32;
    float acc[4][4][4] = {};
    for (int k0 = 0; k0 < 512; k0 += 32) {
        load_nt<128, 256>(As, A, NN, i0, k0, t);
        load_nn<128, 256>(Bs, Bm, RDC, k0, t0, t);
        __syncthreads();
        compute_tile<4, 4, false>(As, &Bs[0][0], acc, wm0, wn0, lane);
        __syncthreads();
    }
    const int grp = lane >> 2, tid4 = lane & 3;
#pragma unroll
    for (int mt = 0; mt < 4; mt++)
#pragma unroll
        for (int nt = 0; nt < 4; nt++)
#pragma unroll
            for (int f = 0; f < 4; f++) {
                int ii = i0 + wm0 + mt * 16 + grp + ((f >= 2) ? 8 : 0);
                int tt = t0 + wn0 + nt * 8 + tid4 * 2 + (f & 1);
                g_o[(((size_t)h << 9) + ii) * RDC + tt] = acc[mt][nt][f];
            }
}

// =============================================================================
// final GEMM (tensor core): 65536 x 128, K=256, A gathered from g_o layout
// =============================================================================
__global__ __launch_bounds__(256) void out_gemm_tc(const float* __restrict__ Wout,
                                                   const float* __restrict__ b_out,
                                                   float* __restrict__ out) {
    __shared__ float As[128][36];
    __shared__ float Bs[32][136];
    const int t = threadIdx.x, lane = t & 31, warp = t >> 5;
    const int m0 = blockIdx.y * 128;
    const int wm0 = (warp >> 2) * 64, wn0 = (warp & 3) * 32;
    float acc[4][4][4] = {};
    for (int k0 = 0; k0 < 256; k0 += 32) {
        // gather A tile: k = (h,d) with h = k0>>5 fixed per tile, d = kq..kq+3
        const int h = k0 >> 5;
#pragma unroll
        for (int i = 0; i < 4; i++) {
            int ml = (t >> 3) + i * 32;
            int m  = m0 + ml;
            int r  = m >> 9, n = m & 511;
            int kq = (t & 7) * 4;
            float4 v = *reinterpret_cast<const float4*>(
                &g_o[(((size_t)h << 9) + n) * RDC + (r << 5) + kq]);
            As[ml][kq + 0] = tf32r(v.x); As[ml][kq + 1] = tf32r(v.y);
            As[ml][kq + 2] = tf32r(v.z); As[ml][kq + 3] = tf32r(v.w);
        }
        load_nn<128, 256>(Bs, Wout, 128, k0, 0, t);
        __syncthreads();
        compute_tile<4, 4, false>(As, &Bs[0][0], acc, wm0, wn0, lane);
        __syncthreads();
    }
    const int grp = lane >> 2, tid4 = lane & 3;
#pragma unroll
    for (int mt = 0; mt < 4; mt++)
#pragma unroll
        for (int nt = 0; nt < 4; nt++)
#pragma unroll
            for (int f = 0; f < 4; f++) {
                int m = m0 + wm0 + mt * 16 + grp + ((f >= 2) ? 8 : 0);
                int c = wn0 + nt * 8 + tid4 * 2 + (f & 1);
                out[(size_t)m * 128 + c] = acc[mt][nt][f] + b_out[c];
            }
}

// =============================================================================
extern "C" void kernel_launch(void* const* d_in, const int* in_sizes, int n_in,
                              void* d_out, int out_size) {
    (void)in_sizes; (void)n_in; (void)out_size;
    const float* x         = (const float*)d_in[0];
    const float* pair_bias = (const float*)d_in[1];
    const float* Wq        = (const float*)d_in[2];
    const float* Wkv       = (const float*)d_in[3];
    const float* Wout      = (const float*)d_in[4];
    const float* b_out     = (const float*)d_in[5];
    const float* ln_g      = (const float*)d_in[6];
    const float* ln_b      = (const float*)d_in[7];
    const float* Wpair     = (const float*)d_in[8];
    const float* Wq_sw     = (const float*)d_in[9];
    const float* bq_sw     = (const float*)d_in[10];
    const float* Wk_sw     = (const float*)d_in[11];
    const float* bk_sw     = (const float*)d_in[12];
    float* out = (float*)d_out;

    qsw_kernel         <<<NN, 128>>>(x, Wq_sw, bq_sw);
    ksw_gemm_tc        <<<dim3(1, 512), 256>>>(x, Wk_sw, bk_sw);
    sw_reduce_kernel   <<<MRN, 128>>>();
    wrow_softmax_kernel<<<NN * HH, 128>>>();
    qkv_gemm_tc        <<<dim3(6, 512), 256>>>(x, Wq, Wkv);
    pbh_kernel         <<<NN * NN / 8, 256>>>(pair_bias, ln_g, ln_b, Wpair);
    dots_gemm_tc       <<<dim3(8, 8, 8), 128>>>();
    attn_softmax_kernel<<<HH * NN, 256>>>();
    o_gemm_tc          <<<dim3(32, 4, 8), 256>>>();
    out_gemm_tc        <<<dim3(1, 512), 256>>>(Wout, b_out, out);
}

// round 3
// speedup vs baseline: 1.5938x; 1.0070x over previous
#include <cuda_runtime.h>
#include <cstdint>

// Problem constants
#define RR   128
#define NN   512
#define DIMC 128
#define HH   8
#define DHC  32
#define DPP  128
#define INNERC 256
#define RDC  4096      // R*DH fused contraction axis
#define MRN  65536     // R*N

// ---------------- scratch (device globals) ------------------------------------
__device__ __align__(16) float g_q   [HH * NN * RDC];
__device__ __align__(16) float g_k   [HH * NN * RDC];
__device__ __align__(16) float g_v   [HH * NN * RDC];
__device__ __align__(16) float g_o   [HH * NN * RDC];
__device__ __align__(16) float g_ksw [MRN * DIMC];
__device__ __align__(16) float g_qsw [NN * DIMC];
__device__ __align__(16) float g_wrow[NN * HH * RR];
__device__ __align__(16) float g_dots[HH * NN * NN];
__device__ __align__(16) float g_pbh [HH * NN * NN];

// ---------------- tf32 helpers -------------------------------------------------
__device__ __forceinline__ float tf32r(float x) {
    uint32_t u;
    asm("cvt.rna.tf32.f32 %0, %1;" : "=r"(u) : "f"(x));
    return __uint_as_float(u);
}

__device__ __forceinline__ void mma8(float* c, const float* a, const float* b) {
    asm volatile(
        "mma.sync.aligned.m16n8k8.row.col.f32.tf32.tf32.f32 "
        "{%0,%1,%2,%3},{%4,%5,%6,%7},{%8,%9},{%0,%1,%2,%3};\n"
        : "+f"(c[0]), "+f"(c[1]), "+f"(c[2]), "+f"(c[3])
        : "r"(__float_as_uint(a[0])), "r"(__float_as_uint(a[1])),
          "r"(__float_as_uint(a[2])), "r"(__float_as_uint(a[3])),
          "r"(__float_as_uint(b[0])), "r"(__float_as_uint(b[1])));
}

// NT stage: tile [BM rows][32 k] from row-major src (k contiguous) -> As[m][36]
template<int BM, int NTHREADS>
__device__ __forceinline__ void load_nt(float (*As)[36], const float* __restrict__ src,
                                        int ld, int row0, int k0, int t) {
#pragma unroll
    for (int i = 0; i < BM * 8 / NTHREADS; i++) {
        int m  = (t >> 3) + i * (NTHREADS / 8);
        int kq = (t & 7) * 4;
        float4 v = *reinterpret_cast<const float4*>(src + (size_t)(row0 + m) * ld + k0 + kq);
        As[m][kq + 0] = tf32r(v.x); As[m][kq + 1] = tf32r(v.y);
        As[m][kq + 2] = tf32r(v.z); As[m][kq + 3] = tf32r(v.w);
    }
}

// NN stage: tile [32 k][BN cols] from row-major src (n contiguous) -> Bs[k][136]
template<int BN, int NTHREADS>
__device__ __forceinline__ void load_nn(float (*Bs)[136], const float* __restrict__ src,
                                        int ld, int k0, int col0, int t) {
#pragma unroll
    for (int i = 0; i < 32 * BN / 4 / NTHREADS; i++) {
        int k  = t / (BN / 4) + i * (NTHREADS / (BN / 4));
        int n4 = (t % (BN / 4)) * 4;
        float4 v = *reinterpret_cast<const float4*>(src + (size_t)(k0 + k) * ld + col0 + n4);
        Bs[k][n4 + 0] = tf32r(v.x); Bs[k][n4 + 1] = tf32r(v.y);
        Bs[k][n4 + 2] = tf32r(v.z); Bs[k][n4 + 3] = tf32r(v.w);
    }
}

// warp compute over one 32-deep k tile.  A: As[m][36].  B: NT -> [n][36], NN -> [k][136]
template<int MT, int NTILES, bool BNT>
__device__ __forceinline__ void compute_tile(const float (*As)[36], const float* BsRaw,
                                             float acc[MT][NTILES][4],
                                             int wm0, int wn0, int lane) {
    const int grp = lane >> 2, tid4 = lane & 3;
    const float (*BsT)[36]  = reinterpret_cast<const float (*)[36]>(BsRaw);
    const float (*BsN)[136] = reinterpret_cast<const float (*)[136]>(BsRaw);
#pragma unroll
    for (int kk = 0; kk < 32; kk += 8) {
        float a[MT][4];
#pragma unroll
        for (int mt = 0; mt < MT; mt++) {
            int mb = wm0 + mt * 16 + grp;
            a[mt][0] = As[mb][kk + tid4];
            a[mt][1] = As[mb + 8][kk + tid4];
            a[mt][2] = As[mb][kk + tid4 + 4];
            a[mt][3] = As[mb + 8][kk + tid4 + 4];
        }
        float b[NTILES][2];
#pragma unroll
        for (int nt = 0; nt < NTILES; nt++) {
            int nb = wn0 + nt * 8 + grp;
            if (BNT) {
                b[nt][0] = BsT[nb][kk + tid4];
                b[nt][1] = BsT[nb][kk + tid4 + 4];
            } else {
                b[nt][0] = BsN[kk + tid4][nb];
                b[nt][1] = BsN[kk + tid4 + 4][nb];
            }
        }
#pragma unroll
        for (int mt = 0; mt < MT; mt++)
#pragma unroll
            for (int nt = 0; nt < NTILES; nt++) mma8(acc[mt][nt], a[mt], b[nt]);
    }
}

// =============================================================================
// q_sw = x[0] @ Wq_sw + bq_sw      (tiny, fp32)
// =============================================================================
__global__ void qsw_kernel(const float* __restrict__ x,
                           const float* __restrict__ Wq_sw,
                           const float* __restrict__ bq_sw) {
    int n = blockIdx.x, c = threadIdx.x;
    __shared__ float xr[DIMC];
    xr[c] = x[(size_t)n * DIMC + c];
    __syncthreads();
    float acc = bq_sw[c];
#pragma unroll 8
    for (int k = 0; k < DIMC; k++) acc += xr[k] * Wq_sw[k * DIMC + c];
    g_qsw[n * DIMC + c] = acc;
}

// =============================================================================
// ksw GEMM (tensor core): 65536 x 128, K=128
// =============================================================================
__global__ __launch_bounds__(256) void ksw_gemm_tc(const float* __restrict__ x,
                                                   const float* __restrict__ Wk_sw,
                                                   const float* __restrict__ bk_sw) {
    __shared__ float As[128][36];
    __shared__ float Bs[32][136];
    const int t = threadIdx.x, lane = t & 31, warp = t >> 5;
    const int m0 = blockIdx.y * 128;
    const int wm0 = (warp >> 2) * 64, wn0 = (warp & 3) * 32;
    float acc[4][4][4] = {};
    for (int k0 = 0; k0 < 128; k0 += 32) {
        load_nt<128, 256>(As, x, 128, m0, k0, t);
        load_nn<128, 256>(Bs, Wk_sw, 128, k0, 0, t);
        __syncthreads();
        compute_tile<4, 4, false>(As, &Bs[0][0], acc, wm0, wn0, lane);
        __syncthreads();
    }
    const int grp = lane >> 2, tid4 = lane & 3;
#pragma unroll
    for (int mt = 0; mt < 4; mt++)
#pragma unroll
        for (int nt = 0; nt < 4; nt++)
#pragma unroll
            for (int f = 0; f < 4; f++) {
                int m = m0 + wm0 + mt * 16 + grp + ((f >= 2) ? 8 : 0);
                int c = wn0 + nt * 8 + tid4 * 2 + (f & 1);
                g_ksw[(size_t)m * 128 + c] = acc[mt][nt][f] + bk_sw[c];
            }
}

// =============================================================================
// sw reduce + row softmax (unchanged, fp32)
// =============================================================================
__global__ void sw_reduce_kernel() {
    int m = blockIdx.x;
    int r = m >> 9, n = m & 511;
    int c = threadIdx.x;
    float prod = g_ksw[(size_t)m * 128 + c] * g_qsw[n * 128 + c];
#pragma unroll
    for (int o = 8; o; o >>= 1) prod += __shfl_down_sync(0xffffffffu, prod, o, 16);
    if ((c & 15) == 0) g_wrow[(n * HH + (c >> 4)) * RR + r] = prod * 0.25f;
}

__global__ void wrow_softmax_kernel() {
    int row = blockIdx.x, t = threadIdx.x;
    float v = g_wrow[(size_t)row * 128 + t];
    __shared__ float sm[128];
    sm[t] = v; __syncthreads();
#pragma unroll
    for (int s = 64; s > 0; s >>= 1) { if (t < s) sm[t] = fmaxf(sm[t], sm[t + s]); __syncthreads(); }
    float mx = sm[0]; __syncthreads();
    float e = expf(v - mx);
    sm[t] = e; __syncthreads();
#pragma unroll
    for (int s = 64; s > 0; s >>= 1) { if (t < s) sm[t] += sm[t + s]; __syncthreads(); }
    g_wrow[(size_t)row * 128 + t] = e / sm[0];
}

// =============================================================================
// QKV GEMM (tensor core): 65536 x 768, K=128; epilogue scatter + w_row on q
// =============================================================================
__global__ __launch_bounds__(256) void qkv_gemm_tc(const float* __restrict__ x,
                                                   const float* __restrict__ Wq,
                                                   const float* __restrict__ Wkv) {
    __shared__ float As[128][36];
    __shared__ float Bs[32][136];
    const int t = threadIdx.x, lane = t & 31, warp = t >> 5;
    const int m0 = blockIdx.y * 128, c0 = blockIdx.x * 128;
    const int wm0 = (warp >> 2) * 64, wn0 = (warp & 3) * 32;
    const float* B; int ldB, cb;
    if (c0 < 256) { B = Wq;  ldB = 256; cb = c0; }
    else          { B = Wkv; ldB = 512; cb = c0 - 256; }
    float acc[4][4][4] = {};
    for (int k0 = 0; k0 < 128; k0 += 32) {
        load_nt<128, 256>(As, x, 128, m0, k0, t);
        load_nn<128, 256>(Bs, B, ldB, k0, cb, t);
        __syncthreads();
        compute_tile<4, 4, false>(As, &Bs[0][0], acc, wm0, wn0, lane);
        __syncthreads();
    }
    const int grp = lane >> 2, tid4 = lane & 3;
#pragma unroll
    for (int mt = 0; mt < 4; mt++)
#pragma unroll
        for (int nt = 0; nt < 4; nt++)
#pragma unroll
            for (int f = 0; f < 4; f++) {
                int m = m0 + wm0 + mt * 16 + grp + ((f >= 2) ? 8 : 0);
                int c = c0 + wn0 + nt * 8 + tid4 * 2 + (f & 1);
                int r = m >> 9, n = m & 511;
                float val = acc[mt][nt][f];
                if (c < 256) {
                    int h = c >> 5, d = c & 31;
                    val *= g_wrow[(n * HH + h) * RR + r];
                    g_q[(((size_t)h << 9) + n) * RDC + (r << 5) + d] = val;
                } else if (c < 512) {
                    int cc = c - 256, h = cc >> 5, d = cc & 31;
                    g_k[(((size_t)h << 9) + n) * RDC + (r << 5) + d] = val;
                } else {
                    int cc = c - 512, h = cc >> 5, d = cc & 31;
                    g_v[(((size_t)h << 9) + n) * RDC + (r << 5) + d] = val;
                }
            }
}

// =============================================================================
// pair bias LN + head projection (unchanged)
// =============================================================================
__global__ void pbh_kernel(const float* __restrict__ pair_bias,
                           const float* __restrict__ ln_g,
                           const float* __restrict__ ln_b,
                           const float* __restrict__ Wpair) {
    int warp = threadIdx.x >> 5, lane = threadIdx.x & 31;
    int idx = blockIdx.x * 8 + warp;
    int i = idx >> 9, j = idx & 511;
    float4 v = *reinterpret_cast<const float4*>(&pair_bias[(size_t)idx * 128 + lane * 4]);
    float s  = v.x + v.y + v.z + v.w;
    float sq = v.x * v.x + v.y * v.y + v.z * v.z + v.w * v.w;
#pragma unroll
    for (int o = 16; o; o >>= 1) {
        s  += __shfl_xor_sync(0xffffffffu, s, o);
        sq += __shfl_xor_sync(0xffffffffu, sq, o);
    }
    float mean = s * (1.0f / 128.0f);
    float var  = sq * (1.0f / 128.0f) - mean * mean;
    float rstd = rsqrtf(var + 1e-5f);
    float vv[4] = {v.x, v.y, v.z, v.w};
    float ph[8] = {};
#pragma unroll
    for (int e = 0; e < 4; e++) {
        int p = lane * 4 + e;
        float nz = (vv[e] - mean) * rstd * ln_g[p] + ln_b[p];
#pragma unroll
        for (int h = 0; h < 8; h++) ph[h] += nz * Wpair[p * 8 + h];
    }
#pragma unroll
    for (int h = 0; h < 8; h++)
#pragma unroll
        for (int o = 16; o; o >>= 1) ph[h] += __shfl_xor_sync(0xffffffffu, ph[h], o);
    if (lane == 0) {
#pragma unroll
        for (int h = 0; h < 8; h++)
            g_pbh[(((size_t)h << 9) + i) * NN + j] = ph[h];
    }
}

// =============================================================================
// dots GEMM (tensor core, NT): per head 512x512, K=4096.  64x64 tiles, 4 warps.
// =============================================================================
__global__ __launch_bounds__(128) void dots_gemm_tc() {
    const int h = blockIdx.z;
    const float* A  = g_q + ((size_t)h << 21);
    const float* Bm = g_k + ((size_t)h << 21);
    __shared__ float As[64][36];
    __shared__ float Bs[64][36];
    const int t = threadIdx.x, lane = t & 31, warp = t >> 5;
    const int i0 = blockIdx.y * 64, j0 = blockIdx.x * 64;
    const int wm0 = (warp >> 1) * 32, wn0 = (warp & 1) * 32;
    float acc[2][4][4] = {};
    for (int k0 = 0; k0 < 4096; k0 += 32) {
        load_nt<64, 128>(As, A,  RDC, i0, k0, t);
        load_nt<64, 128>(Bs, Bm, RDC, j0, k0, t);
        __syncthreads();
        compute_tile<2, 4, true>(As, &Bs[0][0], acc, wm0, wn0, lane);
        __syncthreads();
    }
    const float scale = 0.17677669529663687f;
    const int grp = lane >> 2, tid4 = lane & 3;
#pragma unroll
    for (int mt = 0; mt < 2; mt++)
#pragma unroll
        for (int nt = 0; nt < 4; nt++)
#pragma unroll
            for (int f = 0; f < 4; f++) {
                int ii = i0 + wm0 + mt * 16 + grp + ((f >= 2) ? 8 : 0);
                int jj = j0 + wn0 + nt * 8 + tid4 * 2 + (f & 1);
                size_t off = (((size_t)h << 9) + ii) * NN + jj;
                g_dots[off] = acc[mt][nt][f] * scale + g_pbh[off];
            }
}

// =============================================================================
// attention softmax over j (512) per (h,i)
// =============================================================================
__global__ void attn_softmax_kernel() {
    size_t row = blockIdx.x;
    int t = threadIdx.x;
    float* p = g_dots + row * NN;
    float v0 = p[t], v1 = p[t + 256];
    __shared__ float sm[256];
    sm[t] = fmaxf(v0, v1); __syncthreads();
#pragma unroll
    for (int s = 128; s > 0; s >>= 1) { if (t < s) sm[t] = fmaxf(sm[t], sm[t + s]); __syncthreads(); }
    float mx = sm[0]; __syncthreads();
    float e0 = expf(v0 - mx), e1 = expf(v1 - mx);
    sm[t] = e0 + e1; __syncthreads();
#pragma unroll
    for (int s = 128; s > 0; s >>= 1) { if (t < s) sm[t] += sm[t + s]; __syncthreads(); }
    float inv = 1.0f / sm[0];
    p[t] = e0 * inv; p[t + 256] = e1 * inv;
}

// =============================================================================
// O GEMM (tensor core, NN): per head 512 x 4096, K=512
// =============================================================================
__global__ __launch_bounds__(256) void o_gemm_tc() {
    const int h = blockIdx.z;
    const float* A  = g_dots + ((size_t)h << 18);
    const float* Bm = g_v    + ((size_t)h << 21);
    __shared__ float As[128][36];
    __shared__ float Bs[32][136];
    const int t = threadIdx.x, lane = t & 31, warp = t >> 5;
    const int i0 = blockIdx.y * 128, t0 = blockIdx.x * 128;
    const int wm0 = (warp >> 2) * 64, wn0 = (warp & 3) * 32;
    float acc[4][4][4] = {};
    for (int k0 = 0; k0 < 512; k0 += 32) {
        load_nt<128, 256>(As, A, NN, i0, k0, t);
        load_nn<128, 256>(Bs, Bm, RDC, k0, t0, t);
        __syncthreads();
        compute_tile<4, 4, false>(As, &Bs[0][0], acc, wm0, wn0, lane);
        __syncthreads();
    }
    const int grp = lane >> 2, tid4 = lane & 3;
#pragma unroll
    for (int mt = 0; mt < 4; mt++)
#pragma unroll
        for (int nt = 0; nt < 4; nt++)
#pragma unroll
            for (int f = 0; f < 4; f++) {
                int ii = i0 + wm0 + mt * 16 + grp + ((f >= 2) ? 8 : 0);
                int tt = t0 + wn0 + nt * 8 + tid4 * 2 + (f & 1);
                g_o[(((size_t)h << 9) + ii) * RDC + tt] = acc[mt][nt][f];
            }
}

// =============================================================================
// final GEMM (tensor core): 65536 x 128, K=256, A gathered from g_o layout
// =============================================================================
__global__ __launch_bounds__(256) void out_gemm_tc(const float* __restrict__ Wout,
                                                   const float* __restrict__ b_out,
                                                   float* __restrict__ out) {
    __shared__ float As[128][36];
    __shared__ float Bs[32][136];
    const int t = threadIdx.x, lane = t & 31, warp = t >> 5;
    const int m0 = blockIdx.y * 128;
    const int wm0 = (warp >> 2) * 64, wn0 = (warp & 3) * 32;
    float acc[4][4][4] = {};
    for (int k0 = 0; k0 < 256; k0 += 32) {
        // gather A tile: k = (h,d) with h = k0>>5 fixed per tile, d = kq..kq+3
        const int h = k0 >> 5;
#pragma unroll
        for (int i = 0; i < 4; i++) {
            int ml = (t >> 3) + i * 32;
            int m  = m0 + ml;
            int r  = m >> 9, n = m & 511;
            int kq = (t & 7) * 4;
            float4 v = *reinterpret_cast<const float4*>(
                &g_o[(((size_t)h << 9) + n) * RDC + (r << 5) + kq]);
            As[ml][kq + 0] = tf32r(v.x); As[ml][kq + 1] = tf32r(v.y);
            As[ml][kq + 2] = tf32r(v.z); As[ml][kq + 3] = tf32r(v.w);
        }
        load_nn<128, 256>(Bs, Wout, 128, k0, 0, t);
        __syncthreads();
        compute_tile<4, 4, false>(As, &Bs[0][0], acc, wm0, wn0, lane);
        __syncthreads();
    }
    const int grp = lane >> 2, tid4 = lane & 3;
#pragma unroll
    for (int mt = 0; mt < 4; mt++)
#pragma unroll
        for (int nt = 0; nt < 4; nt++)
#pragma unroll
            for (int f = 0; f < 4; f++) {
                int m = m0 + wm0 + mt * 16 + grp + ((f >= 2) ? 8 : 0);
                int c = wn0 + nt * 8 + tid4 * 2 + (f & 1);
                out[(size_t)m * 128 + c] = acc[mt][nt][f] + b_out[c];
            }
}

// =============================================================================
extern "C" void kernel_launch(void* const* d_in, const int* in_sizes, int n_in,
                              void* d_out, int out_size) {
    (void)in_sizes; (void)n_in; (void)out_size;
    const float* x         = (const float*)d_in[0];
    const float* pair_bias = (const float*)d_in[1];
    const float* Wq        = (const float*)d_in[2];
    const float* Wkv       = (const float*)d_in[3];
    const float* Wout      = (const float*)d_in[4];
    const float* b_out     = (const float*)d_in[5];
    const float* ln_g      = (const float*)d_in[6];
    const float* ln_b      = (const float*)d_in[7];
    const float* Wpair     = (const float*)d_in[8];
    const float* Wq_sw     = (const float*)d_in[9];
    const float* bq_sw     = (const float*)d_in[10];
    const float* Wk_sw     = (const float*)d_in[11];
    const float* bk_sw     = (const float*)d_in[12];
    float* out = (float*)d_out;

    qsw_kernel         <<<NN, 128>>>(x, Wq_sw, bq_sw);
    ksw_gemm_tc        <<<dim3(1, 512), 256>>>(x, Wk_sw, bk_sw);
    sw_reduce_kernel   <<<MRN, 128>>>();
    wrow_softmax_kernel<<<NN * HH, 128>>>();
    qkv_gemm_tc        <<<dim3(6, 512), 256>>>(x, Wq, Wkv);
    pbh_kernel         <<<NN * NN / 8, 256>>>(pair_bias, ln_g, ln_b, Wpair);
    dots_gemm_tc       <<<dim3(8, 8, 8), 128>>>();
    attn_softmax_kernel<<<HH * NN, 256>>>();
    o_gemm_tc          <<<dim3(32, 4, 8), 256>>>();
    out_gemm_tc        <<<dim3(1, 512), 256>>>(Wout, b_out, out);
}

// round 5
// speedup vs baseline: 2.0506x; 1.2866x over previous
#include <cuda_runtime.h>
#include <cuda_fp16.h>
#include <cstdint>

#define NN 512
#define HH 8
#define RDC 4096
#define MRN 65536

// half operand buffers (all NT: rows x contraction-contiguous)
__device__ __align__(16) __half g_xh  [MRN * 128];        // x, half
__device__ __align__(16) __half g_wt  [896 * 128];        // [Wq|Wk|Wv|Wk_sw] cols transposed
__device__ __align__(16) __half g_woutt[128 * 256];       // Wout transposed
__device__ __align__(16) __half g_qh  [HH * NN * RDC];    // [h][n][r*32+d], *w_row
__device__ __align__(16) __half g_kh  [HH * NN * RDC];    // [h][n][r*32+d]
__device__ __align__(16) __half g_vth [HH * RDC * NN];    // [h][t=r*32+d][n]
__device__ __align__(16) __half g_ph  [HH * NN * NN];     // probs [h][i][j]
__device__ __align__(16) __half g_o2  [MRN * 256];        // [(r,n)][(h,d)]
__device__ __align__(16) float  g_dots[HH * NN * NN];     // logits fp32
__device__ __align__(16) float  g_pbh [HH * NN * NN];
__device__ __align__(16) float  g_ksw [MRN * 128];
__device__ __align__(16) float  g_qsw [NN * 128];
__device__ __align__(16) float  g_wrow[NN * HH * 128];

__device__ __forceinline__ uint32_t smem_u32(const void* p) {
    uint32_t a;
    asm("{ .reg .u64 t; cvta.to.shared.u64 t, %1; cvt.u32.u64 %0, t; }" : "=r"(a) : "l"(p));
    return a;
}
__device__ __forceinline__ void ldm4(uint32_t* r, uint32_t addr) {
    asm volatile("ldmatrix.sync.aligned.m8n8.x4.shared.b16 {%0,%1,%2,%3}, [%4];"
                 : "=r"(r[0]), "=r"(r[1]), "=r"(r[2]), "=r"(r[3]) : "r"(addr));
}
__device__ __forceinline__ void mma16(float* c, const uint32_t* a, const uint32_t* b) {
    asm volatile("mma.sync.aligned.m16n8k16.row.col.f32.f16.f16.f32 "
        "{%0,%1,%2,%3},{%4,%5,%6,%7},{%8,%9},{%0,%1,%2,%3};"
        : "+f"(c[0]), "+f"(c[1]), "+f"(c[2]), "+f"(c[3])
        : "r"(a[0]), "r"(a[1]), "r"(a[2]), "r"(a[3]), "r"(b[0]), "r"(b[1]));
}
#define CPA16(dst, src) \
    asm volatile("cp.async.cg.shared.global [%0], [%1], 16;" :: "r"(dst), "l"(src) : "memory")

// ============================================================================
// Unified NT fp16 GEMM: block 128x128, 8 warps (warp 64x32), ktile 32, 2-stage
// MODE: 0=qkv, 1=dots, 2=O, 3=out, 4=ksw
// ============================================================================
template<int MODE, int KT>
__global__ __launch_bounds__(256) void g16(const float* __restrict__ auxA,
                                           float* __restrict__ outp) {
    __shared__ __half As[2][128 * 40];
    __shared__ __half Bs[2][128 * 40];
    const int t = threadIdx.x, lane = t & 31, warp = t >> 5;
    const int bx = blockIdx.x, by = blockIdx.y, h = blockIdx.z;

    const __half *A, *B; int lda, ldb;
    if (MODE == 0)      { A = g_xh + (size_t)by * 128 * 128; lda = 128;
                          B = g_wt + (size_t)bx * 128 * 128; ldb = 128; }
    else if (MODE == 4) { A = g_xh + (size_t)by * 128 * 128; lda = 128;
                          B = g_wt + (size_t)768 * 128;      ldb = 128; }
    else if (MODE == 1) { A = g_qh + ((size_t)h * 512 + by * 128) * 4096; lda = 4096;
                          B = g_kh + ((size_t)h * 512 + bx * 128) * 4096; ldb = 4096; }
    else if (MODE == 2) { A = g_ph  + ((size_t)h * 512  + by * 128) * 512; lda = 512;
                          B = g_vth + ((size_t)h * 4096 + bx * 128) * 512; ldb = 512; }
    else                { A = g_o2 + (size_t)by * 128 * 256; lda = 256;
                          B = g_woutt;                       ldb = 256; }

    auto cpst = [&](int st, int k0) {
        uint32_t da = smem_u32(&As[st][0]), db = smem_u32(&Bs[st][0]);
#pragma unroll
        for (int c = t; c < 512; c += 256) {
            int row = c >> 2, col = c & 3;
            CPA16(da + row * 80 + col * 16, A + (size_t)row * lda + k0 + col * 8);
            CPA16(db + row * 80 + col * 16, B + (size_t)row * ldb + k0 + col * 8);
        }
        asm volatile("cp.async.commit_group;" ::: "memory");
    };

    float acc[4][4][4] = {};
    const int wm0 = (warp >> 2) * 64, wn0 = (warp & 3) * 32;
    const int q = lane >> 3;

    cpst(0, 0);
    for (int kt = 0; kt < KT; kt++) {
        if (kt + 1 < KT) {
            cpst((kt + 1) & 1, (kt + 1) * 32);
            asm volatile("cp.async.wait_group 1;" ::: "memory");
        } else {
            asm volatile("cp.async.wait_group 0;" ::: "memory");
        }
        __syncthreads();
        uint32_t ab = smem_u32(&As[kt & 1][0]), bb = smem_u32(&Bs[kt & 1][0]);
#pragma unroll
        for (int kk = 0; kk < 32; kk += 16) {
            uint32_t af[4][4], bf[2][4];
#pragma unroll
            for (int mt = 0; mt < 4; mt++)
                ldm4(af[mt], ab + (wm0 + mt * 16 + (lane & 15)) * 80 + (kk + (lane >> 4) * 8) * 2);
#pragma unroll
            for (int np = 0; np < 2; np++)
                ldm4(bf[np], bb + (wn0 + np * 16 + (q >> 1) * 8 + (lane & 7)) * 80 + (kk + (q & 1) * 8) * 2);
#pragma unroll
            for (int mt = 0; mt < 4; mt++)
#pragma unroll
                for (int nt = 0; nt < 4; nt++)
                    mma16(acc[mt][nt], af[mt], &bf[nt >> 1][(nt & 1) * 2]);
        }
        __syncthreads();
    }

    // epilogue
#pragma unroll
    for (int mt = 0; mt < 4; mt++)
#pragma unroll
        for (int nt = 0; nt < 4; nt++)
#pragma unroll
            for (int hf = 0; hf < 2; hf++) {
                int mrow = wm0 + mt * 16 + (lane >> 2) + hf * 8;
                int ncol = wn0 + nt * 8 + (lane & 3) * 2;
                float v0 = acc[mt][nt][hf * 2], v1 = acc[mt][nt][hf * 2 + 1];
                if (MODE == 0) {
                    int m = by * 128 + mrow, c = bx * 128 + ncol;
                    int r = m >> 9, n = m & 511;
                    if (c < 256) {
                        int hh = c >> 5, d = c & 31;
                        float w = g_wrow[(n * 8 + hh) * 128 + r];
                        *reinterpret_cast<__half2*>(
                            &g_qh[((size_t)(hh * 512 + n)) * 4096 + r * 32 + d]) =
                            __floats2half2_rn(v0 * w, v1 * w);
                    } else if (c < 512) {
                        int cc = c - 256, hh = cc >> 5, d = cc & 31;
                        *reinterpret_cast<__half2*>(
                            &g_kh[((size_t)(hh * 512 + n)) * 4096 + r * 32 + d]) =
                            __floats2half2_rn(v0, v1);
                    } else {
                        int cc = c - 512, hh = cc >> 5, d = cc & 31, tt = r * 32 + d;
                        g_vth[((size_t)hh * 4096 + tt) * 512 + n]     = __float2half_rn(v0);
                        g_vth[((size_t)hh * 4096 + tt + 1) * 512 + n] = __float2half_rn(v1);
                    }
                } else if (MODE == 4) {
                    int m = by * 128 + mrow;
                    g_ksw[(size_t)m * 128 + ncol]     = v0 + auxA[ncol];
                    g_ksw[(size_t)m * 128 + ncol + 1] = v1 + auxA[ncol + 1];
                } else if (MODE == 1) {
                    int i = by * 128 + mrow, j = bx * 128 + ncol;
                    size_t off = ((size_t)h * 512 + i) * 512 + j;
                    const float scale = 0.17677669529663687f;
                    g_dots[off]     = v0 * scale + g_pbh[off];
                    g_dots[off + 1] = v1 * scale + g_pbh[off + 1];
                } else if (MODE == 2) {
                    int i = by * 128 + mrow, tcol = bx * 128 + ncol;
                    int r = tcol >> 5, d = tcol & 31;
                    *reinterpret_cast<__half2*>(
                        &g_o2[((size_t)r * 512 + i) * 256 + h * 32 + d]) =
                        __floats2half2_rn(v0, v1);
                } else {
                    int m = by * 128 + mrow;
                    outp[(size_t)m * 128 + ncol]     = v0 + auxA[ncol];
                    outp[(size_t)m * 128 + ncol + 1] = v1 + auxA[ncol + 1];
                }
            }
}

// ============================================================================
// conversions
// ============================================================================
__global__ void conv_x(const float* __restrict__ x) {
    size_t i = ((size_t)blockIdx.x * 256 + threadIdx.x) * 4;
    float4 v = *reinterpret_cast<const float4*>(x + i);
    __half2* d = reinterpret_cast<__half2*>(&g_xh[i]);
    d[0] = __floats2half2_rn(v.x, v.y);
    d[1] = __floats2half2_rn(v.z, v.w);
}

__global__ void conv_w(const float* __restrict__ Wq, const float* __restrict__ Wkv,
                       const float* __restrict__ Wk_sw, const float* __restrict__ Wout) {
    int g = blockIdx.x * 256 + threadIdx.x;
    if (g < 114688) {
        int row = g >> 7, k = g & 127;
        float v;
        if (row < 256)      v = Wq[k * 256 + row];
        else if (row < 768) v = Wkv[k * 512 + (row - 256)];
        else                v = Wk_sw[k * 128 + (row - 768)];
        g_wt[g] = __float2half_rn(v);
    } else {
        int g2 = g - 114688;
        int c = g2 >> 8, k = g2 & 255;
        g_woutt[g2] = __float2half_rn(Wout[k * 128 + c]);
    }
}

// ============================================================================
// small fp32 kernels
// ============================================================================
__global__ void qsw_kernel(const float* __restrict__ x, const float* __restrict__ Wq_sw,
                           const float* __restrict__ bq_sw) {
    int n = blockIdx.x, c = threadIdx.x;
    __shared__ float xr[128];
    xr[c] = x[(size_t)n * 128 + c];
    __syncthreads();
    float acc = bq_sw[c];
#pragma unroll 8
    for (int k = 0; k < 128; k++) acc += xr[k] * Wq_sw[k * 128 + c];
    g_qsw[n * 128 + c] = acc;
}

__global__ void sw_reduce_kernel() {
    int m = blockIdx.x, r = m >> 9, n = m & 511, c = threadIdx.x;
    float prod = g_ksw[(size_t)m * 128 + c] * g_qsw[n * 128 + c];
#pragma unroll
    for (int o = 8; o; o >>= 1) prod += __shfl_down_sync(0xffffffffu, prod, o, 16);
    if ((c & 15) == 0) g_wrow[(n * 8 + (c >> 4)) * 128 + r] = prod * 0.25f;
}

__global__ void wrow_softmax_kernel() {
    int row = blockIdx.x, t = threadIdx.x;
    float v = g_wrow[(size_t)row * 128 + t];
    __shared__ float sm[128];
    sm[t] = v; __syncthreads();
#pragma unroll
    for (int s = 64; s > 0; s >>= 1) { if (t < s) sm[t] = fmaxf(sm[t], sm[t + s]); __syncthreads(); }
    float mx = sm[0]; __syncthreads();
    float e = expf(v - mx);
    sm[t] = e; __syncthreads();
#pragma unroll
    for (int s = 64; s > 0; s >>= 1) { if (t < s) sm[t] += sm[t + s]; __syncthreads(); }
    g_wrow[(size_t)row * 128 + t] = e / sm[0];
}

__global__ void pbh_kernel(const float* __restrict__ pair_bias, const float* __restrict__ ln_g,
                           const float* __restrict__ ln_b, const float* __restrict__ Wpair) {
    int warp = threadIdx.x >> 5, lane = threadIdx.x & 31;
    int idx = blockIdx.x * 8 + warp;
    int i = idx >> 9, j = idx & 511;
    float4 v = *reinterpret_cast<const float4*>(&pair_bias[(size_t)idx * 128 + lane * 4]);
    float s  = v.x + v.y + v.z + v.w;
    float sq = v.x * v.x + v.y * v.y + v.z * v.z + v.w * v.w;
#pragma unroll
    for (int o = 16; o; o >>= 1) {
        s  += __shfl_xor_sync(0xffffffffu, s, o);
        sq += __shfl_xor_sync(0xffffffffu, sq, o);
    }
    float mean = s * (1.0f / 128.0f);
    float var  = sq * (1.0f / 128.0f) - mean * mean;
    float rstd = rsqrtf(var + 1e-5f);
    float vv[4] = {v.x, v.y, v.z, v.w};
    float ph[8] = {};
#pragma unroll
    for (int e = 0; e < 4; e++) {
        int p = lane * 4 + e;
        float nz = (vv[e] - mean) * rstd * ln_g[p] + ln_b[p];
#pragma unroll
        for (int h = 0; h < 8; h++) ph[h] += nz * Wpair[p * 8 + h];
    }
#pragma unroll
    for (int h = 0; h < 8; h++)
#pragma unroll
        for (int o = 16; o; o >>= 1) ph[h] += __shfl_xor_sync(0xffffffffu, ph[h], o);
    if (lane == 0)
#pragma unroll
        for (int h = 0; h < 8; h++) g_pbh[(((size_t)h << 9) + i) * NN + j] = ph[h];
}

__global__ void attn_softmax_kernel() {
    size_t row = blockIdx.x;
    int t = threadIdx.x;
    const float* p = g_dots + row * 512;
    float v0 = p[t], v1 = p[t + 256];
    __shared__ float sm[256];
    sm[t] = fmaxf(v0, v1); __syncthreads();
#pragma unroll
    for (int s = 128; s > 0; s >>= 1) { if (t < s) sm[t] = fmaxf(sm[t], sm[t + s]); __syncthreads(); }
    float mx = sm[0]; __syncthreads();
    float e0 = expf(v0 - mx), e1 = expf(v1 - mx);
    sm[t] = e0 + e1; __syncthreads();
#pragma unroll
    for (int s = 128; s > 0; s >>= 1) { if (t < s) sm[t] += sm[t + s]; __syncthreads(); }
    float inv = 1.0f / sm[0];
    g_ph[row * 512 + t]       = __float2half_rn(e0 * inv);
    g_ph[row * 512 + t + 256] = __float2half_rn(e1 * inv);
}

// ============================================================================
extern "C" void kernel_launch(void* const* d_in, const int* in_sizes, int n_in,
                              void* d_out, int out_size) {
    (void)in_sizes; (void)n_in; (void)out_size;
    const float* x         = (const float*)d_in[0];
    const float* pair_bias = (const float*)d_in[1];
    const float* Wq        = (const float*)d_in[2];
    const float* Wkv       = (const float*)d_in[3];
    const float* Wout      = (const float*)d_in[4];
    const float* b_out     = (const float*)d_in[5];
    const float* ln_g      = (const float*)d_in[6];
    const float* ln_b      = (const float*)d_in[7];
    const float* Wpair     = (const float*)d_in[8];
    const float* Wq_sw     = (const float*)d_in[9];
    const float* bq_sw     = (const float*)d_in[10];
    const float* Wk_sw     = (const float*)d_in[11];
    const float* bk_sw     = (const float*)d_in[12];
    float* out = (float*)d_out;

    conv_x             <<<8192, 256>>>(x);
    conv_w             <<<576, 256>>>(Wq, Wkv, Wk_sw, Wout);
    qsw_kernel         <<<NN, 128>>>(x, Wq_sw, bq_sw);
    g16<4, 4>          <<<dim3(1, 512), 256>>>(bk_sw, nullptr);     // ksw
    sw_reduce_kernel   <<<MRN, 128>>>();
    wrow_softmax_kernel<<<NN * HH, 128>>>();
    g16<0, 4>          <<<dim3(6, 512), 256>>>(nullptr, nullptr);   // qkv
    pbh_kernel         <<<NN * NN / 8, 256>>>(pair_bias, ln_g, ln_b, Wpair);
    g16<1, 128>        <<<dim3(4, 4, 8), 256>>>(nullptr, nullptr);  // dots
    attn_softmax_kernel<<<HH * NN, 256>>>();
    g16<2, 16>         <<<dim3(32, 4, 8), 256>>>(nullptr, nullptr); // O
    g16<3, 8>          <<<dim3(1, 512), 256>>>(b_out, out);         // out
}

// round 6
// speedup vs baseline: 2.1140x; 1.0309x over previous
#include <cuda_runtime.h>
#include <cuda_fp16.h>
#include <cstdint>

#define NN 512
#define HH 8
#define RDC 4096
#define MRN 65536
#define DPL 2097152   // one dots plane = 8*512*512

// half operand buffers
__device__ __align__(16) __half g_xh  [MRN * 128];
__device__ __align__(16) __half g_wt  [896 * 128];        // [Wq|Wk|Wv|Wk_sw] transposed
__device__ __align__(16) __half g_woutt[128 * 256];
__device__ __align__(16) __half g_qh  [HH * NN * RDC];    // [h][n][r*32+d] * w_row
__device__ __align__(16) __half g_kh  [HH * NN * RDC];    // [h][n][r*32+d]
__device__ __align__(16) __half g_vh  [HH * NN * RDC];    // [h][n][r*32+d]  (coalesced!)
__device__ __align__(16) __half g_ph  [HH * NN * NN];     // probs [h][i][j]
__device__ __align__(16) __half g_o2  [MRN * 256];        // [(r,n)][(h,d)]
__device__ __align__(16) float  g_dots[2 * DPL];          // split-K partials
__device__ __align__(16) float  g_pbh [HH * NN * NN];
__device__ __align__(16) float  g_ksw [MRN * 128];
__device__ __align__(16) float  g_qsw [NN * 128];
__device__ __align__(16) float  g_wrow[NN * HH * 128];

__device__ __forceinline__ uint32_t smem_u32(const void* p) {
    uint32_t a;
    asm("{ .reg .u64 t; cvta.to.shared.u64 t, %1; cvt.u32.u64 %0, t; }" : "=r"(a) : "l"(p));
    return a;
}
__device__ __forceinline__ void ldm4(uint32_t* r, uint32_t addr) {
    asm volatile("ldmatrix.sync.aligned.m8n8.x4.shared.b16 {%0,%1,%2,%3}, [%4];"
                 : "=r"(r[0]), "=r"(r[1]), "=r"(r[2]), "=r"(r[3]) : "r"(addr));
}
__device__ __forceinline__ void ldm4t(uint32_t* r, uint32_t addr) {
    asm volatile("ldmatrix.sync.aligned.m8n8.x4.trans.shared.b16 {%0,%1,%2,%3}, [%4];"
                 : "=r"(r[0]), "=r"(r[1]), "=r"(r[2]), "=r"(r[3]) : "r"(addr));
}
__device__ __forceinline__ void mma16(float* c, const uint32_t* a, const uint32_t* b) {
    asm volatile("mma.sync.aligned.m16n8k16.row.col.f32.f16.f16.f32 "
        "{%0,%1,%2,%3},{%4,%5,%6,%7},{%8,%9},{%0,%1,%2,%3};"
        : "+f"(c[0]), "+f"(c[1]), "+f"(c[2]), "+f"(c[3])
        : "r"(a[0]), "r"(a[1]), "r"(a[2]), "r"(a[3]), "r"(b[0]), "r"(b[1]));
}
#define CPA16(dst, src) \
    asm volatile("cp.async.cg.shared.global [%0], [%1], 16;" :: "r"(dst), "l"(src) : "memory")

// ============================================================================
// Unified fp16 GEMM: block 128x128, 8 warps (warp 64x32), ktile 32, 2-stage.
// MODE: 0=qkv, 1=dots(split-K via z), 2=O (trans-B from g_vh), 3=out, 4=ksw
// ============================================================================
template<int MODE, int KT>
__global__ __launch_bounds__(256) void g16(const float* __restrict__ auxA,
                                           float* __restrict__ outp) {
    __shared__ __half As[2][128 * 40];
    __shared__ __half Bs[2][128 * 40];
    const int t = threadIdx.x, lane = t & 31, warp = t >> 5;
    const int bx = blockIdx.x, by = blockIdx.y;
    const int h = (MODE == 1) ? (blockIdx.z & 7) : blockIdx.z;
    const int split = (MODE == 1) ? (blockIdx.z >> 3) : 0;

    const __half *A, *B; int lda, ldb;
    if (MODE == 0)      { A = g_xh + (size_t)by * 128 * 128; lda = 128;
                          B = g_wt + (size_t)bx * 128 * 128; ldb = 128; }
    else if (MODE == 4) { A = g_xh + (size_t)by * 128 * 128; lda = 128;
                          B = g_wt + (size_t)768 * 128;      ldb = 128; }
    else if (MODE == 1) { A = g_qh + ((size_t)h * 512 + by * 128) * 4096 + split * 2048; lda = 4096;
                          B = g_kh + ((size_t)h * 512 + bx * 128) * 4096 + split * 2048; ldb = 4096; }
    else if (MODE == 2) { A = g_ph + ((size_t)h * 512 + by * 128) * 512; lda = 512;
                          B = g_vh + (size_t)h * 512 * 4096 + bx * 128;  ldb = 4096; }  // rows = j
    else                { A = g_o2 + (size_t)by * 128 * 256; lda = 256;
                          B = g_woutt;                       ldb = 256; }

    auto cpst = [&](int st, int k0) {
        uint32_t da = smem_u32(&As[st][0]), db = smem_u32(&Bs[st][0]);
#pragma unroll
        for (int c = t; c < 512; c += 256) {
            int row = c >> 2, col = c & 3;
            CPA16(da + row * 80 + col * 16, A + (size_t)row * lda + k0 + col * 8);
        }
        if (MODE == 2) {
#pragma unroll
            for (int c = t; c < 512; c += 256) {
                int row = c >> 4, col = c & 15;   // [32 k][128 n] tile
                CPA16(db + row * 272 + col * 16, B + (size_t)(k0 + row) * ldb + col * 8);
            }
        } else {
#pragma unroll
            for (int c = t; c < 512; c += 256) {
                int row = c >> 2, col = c & 3;
                CPA16(db + row * 80 + col * 16, B + (size_t)row * ldb + k0 + col * 8);
            }
        }
        asm volatile("cp.async.commit_group;" ::: "memory");
    };

    float acc[4][4][4] = {};
    const int wm0 = (warp >> 2) * 64, wn0 = (warp & 3) * 32;
    const int q = lane >> 3;

    cpst(0, 0);
    for (int kt = 0; kt < KT; kt++) {
        if (kt + 1 < KT) {
            cpst((kt + 1) & 1, (kt + 1) * 32);
            asm volatile("cp.async.wait_group 1;" ::: "memory");
        } else {
            asm volatile("cp.async.wait_group 0;" ::: "memory");
        }
        __syncthreads();
        uint32_t ab = smem_u32(&As[kt & 1][0]), bb = smem_u32(&Bs[kt & 1][0]);
#pragma unroll
        for (int kk = 0; kk < 32; kk += 16) {
            uint32_t af[4][4], bf[2][4];
#pragma unroll
            for (int mt = 0; mt < 4; mt++)
                ldm4(af[mt], ab + (wm0 + mt * 16 + (lane & 15)) * 80 + (kk + (lane >> 4) * 8) * 2);
#pragma unroll
            for (int np = 0; np < 2; np++) {
                if (MODE == 2)
                    ldm4t(bf[np], bb + (kk + (q & 1) * 8 + (lane & 7)) * 272
                                     + (wn0 + np * 16 + (q >> 1) * 8) * 2);
                else
                    ldm4(bf[np], bb + (wn0 + np * 16 + (q >> 1) * 8 + (lane & 7)) * 80
                                    + (kk + (q & 1) * 8) * 2);
            }
#pragma unroll
            for (int mt = 0; mt < 4; mt++)
#pragma unroll
                for (int nt = 0; nt < 4; nt++)
                    mma16(acc[mt][nt], af[mt], &bf[nt >> 1][(nt & 1) * 2]);
        }
        __syncthreads();
    }

    // epilogue
#pragma unroll
    for (int mt = 0; mt < 4; mt++)
#pragma unroll
        for (int nt = 0; nt < 4; nt++)
#pragma unroll
            for (int hf = 0; hf < 2; hf++) {
                int mrow = wm0 + mt * 16 + (lane >> 2) + hf * 8;
                int ncol = wn0 + nt * 8 + (lane & 3) * 2;
                float v0 = acc[mt][nt][hf * 2], v1 = acc[mt][nt][hf * 2 + 1];
                if (MODE == 0) {
                    int m = by * 128 + mrow, c = bx * 128 + ncol;
                    int r = m >> 9, n = m & 511;
                    if (c < 256) {
                        int hh = c >> 5, d = c & 31;
                        float w = g_wrow[(n * 8 + hh) * 128 + r];
                        *reinterpret_cast<__half2*>(
                            &g_qh[((size_t)(hh * 512 + n)) * 4096 + r * 32 + d]) =
                            __floats2half2_rn(v0 * w, v1 * w);
                    } else if (c < 512) {
                        int cc = c - 256, hh = cc >> 5, d = cc & 31;
                        *reinterpret_cast<__half2*>(
                            &g_kh[((size_t)(hh * 512 + n)) * 4096 + r * 32 + d]) =
                            __floats2half2_rn(v0, v1);
                    } else {
                        int cc = c - 512, hh = cc >> 5, d = cc & 31;
                        *reinterpret_cast<__half2*>(
                            &g_vh[((size_t)(hh * 512 + n)) * 4096 + r * 32 + d]) =
                            __floats2half2_rn(v0, v1);
                    }
                } else if (MODE == 4) {
                    int m = by * 128 + mrow;
                    g_ksw[(size_t)m * 128 + ncol]     = v0 + auxA[ncol];
                    g_ksw[(size_t)m * 128 + ncol + 1] = v1 + auxA[ncol + 1];
                } else if (MODE == 1) {
                    int i = by * 128 + mrow, j = bx * 128 + ncol;
                    size_t off = (size_t)split * DPL + ((size_t)h * 512 + i) * 512 + j;
                    g_dots[off]     = v0;
                    g_dots[off + 1] = v1;
                } else if (MODE == 2) {
                    int i = by * 128 + mrow, tcol = bx * 128 + ncol;
                    int r = tcol >> 5, d = tcol & 31;
                    *reinterpret_cast<__half2*>(
                        &g_o2[((size_t)r * 512 + i) * 256 + h * 32 + d]) =
                        __floats2half2_rn(v0, v1);
                } else {
                    int m = by * 128 + mrow;
                    outp[(size_t)m * 128 + ncol]     = v0 + auxA[ncol];
                    outp[(size_t)m * 128 + ncol + 1] = v1 + auxA[ncol + 1];
                }
            }
}

// ============================================================================
__global__ void conv_x(const float* __restrict__ x) {
    size_t i = ((size_t)blockIdx.x * 256 + threadIdx.x) * 4;
    float4 v = *reinterpret_cast<const float4*>(x + i);
    __half2* d = reinterpret_cast<__half2*>(&g_xh[i]);
    d[0] = __floats2half2_rn(v.x, v.y);
    d[1] = __floats2half2_rn(v.z, v.w);
}

__global__ void conv_w(const float* __restrict__ Wq, const float* __restrict__ Wkv,
                       const float* __restrict__ Wk_sw, const float* __restrict__ Wout) {
    int g = blockIdx.x * 256 + threadIdx.x;
    if (g < 114688) {
        int row = g >> 7, k = g & 127;
        float v;
        if (row < 256)      v = Wq[k * 256 + row];
        else if (row < 768) v = Wkv[k * 512 + (row - 256)];
        else                v = Wk_sw[k * 128 + (row - 768)];
        g_wt[g] = __float2half_rn(v);
    } else {
        int g2 = g - 114688;
        int c = g2 >> 8, k = g2 & 255;
        g_woutt[g2] = __float2half_rn(Wout[k * 128 + c]);
    }
}

__global__ void qsw_kernel(const float* __restrict__ x, const float* __restrict__ Wq_sw,
                           const float* __restrict__ bq_sw) {
    int n = blockIdx.x, c = threadIdx.x;
    __shared__ float xr[128];
    xr[c] = x[(size_t)n * 128 + c];
    __syncthreads();
    float acc = bq_sw[c];
#pragma unroll 8
    for (int k = 0; k < 128; k++) acc += xr[k] * Wq_sw[k * 128 + c];
    g_qsw[n * 128 + c] = acc;
}

__global__ void sw_reduce_kernel() {
    int m = blockIdx.x, r = m >> 9, n = m & 511, c = threadIdx.x;
    float prod = g_ksw[(size_t)m * 128 + c] * g_qsw[n * 128 + c];
#pragma unroll
    for (int o = 8; o; o >>= 1) prod += __shfl_down_sync(0xffffffffu, prod, o, 16);
    if ((c & 15) == 0) g_wrow[(n * 8 + (c >> 4)) * 128 + r] = prod * 0.25f;
}

__global__ void wrow_softmax_kernel() {
    int row = blockIdx.x, t = threadIdx.x;
    float v = g_wrow[(size_t)row * 128 + t];
    __shared__ float sm[128];
    sm[t] = v; __syncthreads();
#pragma unroll
    for (int s = 64; s > 0; s >>= 1) { if (t < s) sm[t] = fmaxf(sm[t], sm[t + s]); __syncthreads(); }
    float mx = sm[0]; __syncthreads();
    float e = expf(v - mx);
    sm[t] = e; __syncthreads();
#pragma unroll
    for (int s = 64; s > 0; s >>= 1) { if (t < s) sm[t] += sm[t + s]; __syncthreads(); }
    g_wrow[(size_t)row * 128 + t] = e / sm[0];
}

__global__ void pbh_kernel(const float* __restrict__ pair_bias, const float* __restrict__ ln_g,
                           const float* __restrict__ ln_b, const float* __restrict__ Wpair) {
    int warp = threadIdx.x >> 5, lane = threadIdx.x & 31;
    int idx = blockIdx.x * 8 + warp;
    int i = idx >> 9, j = idx & 511;
    float4 v = *reinterpret_cast<const float4*>(&pair_bias[(size_t)idx * 128 + lane * 4]);
    float s  = v.x + v.y + v.z + v.w;
    float sq = v.x * v.x + v.y * v.y + v.z * v.z + v.w * v.w;
#pragma unroll
    for (int o = 16; o; o >>= 1) {
        s  += __shfl_xor_sync(0xffffffffu, s, o);
        sq += __shfl_xor_sync(0xffffffffu, sq, o);
    }
    float mean = s * (1.0f / 128.0f);
    float var  = sq * (1.0f / 128.0f) - mean * mean;
    float rstd = rsqrtf(var + 1e-5f);
    float vv[4] = {v.x, v.y, v.z, v.w};
    float ph[8] = {};
#pragma unroll
    for (int e = 0; e < 4; e++) {
        int p = lane * 4 + e;
        float nz = (vv[e] - mean) * rstd * ln_g[p] + ln_b[p];
#pragma unroll
        for (int hh = 0; hh < 8; hh++) ph[hh] += nz * Wpair[p * 8 + hh];
    }
#pragma unroll
    for (int hh = 0; hh < 8; hh++)
#pragma unroll
        for (int o = 16; o; o >>= 1) ph[hh] += __shfl_xor_sync(0xffffffffu, ph[hh], o);
    if (lane == 0)
#pragma unroll
        for (int hh = 0; hh < 8; hh++) g_pbh[(((size_t)hh << 9) + i) * NN + j] = ph[hh];
}

// softmax: combine split-K partials, scale, +pbh, softmax -> half probs
__global__ void attn_softmax_kernel() {
    size_t row = blockIdx.x;
    int t = threadIdx.x;
    size_t off0 = row * 512 + t, off1 = off0 + 256;
    const float scale = 0.17677669529663687f;
    float v0 = (g_dots[off0] + g_dots[off0 + DPL]) * scale + g_pbh[off0];
    float v1 = (g_dots[off1] + g_dots[off1 + DPL]) * scale + g_pbh[off1];
    __shared__ float sm[256];
    sm[t] = fmaxf(v0, v1); __syncthreads();
#pragma unroll
    for (int s = 128; s > 0; s >>= 1) { if (t < s) sm[t] = fmaxf(sm[t], sm[t + s]); __syncthreads(); }
    float mx = sm[0]; __syncthreads();
    float e0 = expf(v0 - mx), e1 = expf(v1 - mx);
    sm[t] = e0 + e1; __syncthreads();
#pragma unroll
    for (int s = 128; s > 0; s >>= 1) { if (t < s) sm[t] += sm[t + s]; __syncthreads(); }
    float inv = 1.0f / sm[0];
    g_ph[row * 512 + t]       = __float2half_rn(e0 * inv);
    g_ph[row * 512 + t + 256] = __float2half_rn(e1 * inv);
}

// ============================================================================
extern "C" void kernel_launch(void* const* d_in, const int* in_sizes, int n_in,
                              void* d_out, int out_size) {
    (void)in_sizes; (void)n_in; (void)out_size;
    const float* x         = (const float*)d_in[0];
    const float* pair_bias = (const float*)d_in[1];
    const float* Wq        = (const float*)d_in[2];
    const float* Wkv       = (const float*)d_in[3];
    const float* Wout      = (const float*)d_in[4];
    const float* b_out     = (const float*)d_in[5];
    const float* ln_g      = (const float*)d_in[6];
    const float* ln_b      = (const float*)d_in[7];
    const float* Wpair     = (const float*)d_in[8];
    const float* Wq_sw     = (const float*)d_in[9];
    const float* bq_sw     = (const float*)d_in[10];
    const float* Wk_sw     = (const float*)d_in[11];
    const float* bk_sw     = (const float*)d_in[12];
    float* out = (float*)d_out;

    conv_x             <<<8192, 256>>>(x);
    conv_w             <<<576, 256>>>(Wq, Wkv, Wk_sw, Wout);
    qsw_kernel         <<<NN, 128>>>(x, Wq_sw, bq_sw);
    g16<4, 4>          <<<dim3(1, 512), 256>>>(bk_sw, nullptr);      // ksw
    sw_reduce_kernel   <<<MRN, 128>>>();
    wrow_softmax_kernel<<<NN * HH, 128>>>();
    g16<0, 4>          <<<dim3(6, 512), 256>>>(nullptr, nullptr);    // qkv
    pbh_kernel         <<<NN * NN / 8, 256>>>(pair_bias, ln_g, ln_b, Wpair);
    g16<1, 64>         <<<dim3(4, 4, 16), 256>>>(nullptr, nullptr);  // dots split-K=2
    attn_softmax_kernel<<<HH * NN, 256>>>();
    g16<2, 16>         <<<dim3(32, 4, 8), 256>>>(nullptr, nullptr);  // O (trans-B)
    g16<3, 8>          <<<dim3(1, 512), 256>>>(b_out, out);          // out
}

// round 8
// speedup vs baseline: 2.1400x; 1.0123x over previous
#include <cuda_runtime.h>
#include <cuda_fp16.h>
#include <cstdint>

#define NN 512
#define HH 8
#define RDC 4096
#define MRN 65536
#define DPL 2097152   // one dots plane = 8*512*512
#define STG_H 5120    // halves per smem stage (128*40)
#define SMEM_BYTES 61440

__device__ __align__(16) __half g_xh  [MRN * 128];
__device__ __align__(16) __half g_wt  [896 * 128];
__device__ __align__(16) __half g_woutt[128 * 256];
__device__ __align__(16) __half g_qh  [HH * NN * RDC];
__device__ __align__(16) __half g_kh  [HH * NN * RDC];
__device__ __align__(16) __half g_vh  [HH * NN * RDC];
__device__ __align__(16) __half g_ph  [HH * NN * NN];
__device__ __align__(16) __half g_o2  [MRN * 256];
__device__ __align__(16) float  g_dots[4 * DPL];
__device__ __align__(16) float  g_pbh [HH * NN * NN];
__device__ __align__(16) float  g_ksw [MRN * 128];
__device__ __align__(16) float  g_qsw [NN * 128];
__device__ __align__(16) float  g_wrow[NN * HH * 128];

__device__ __forceinline__ uint32_t smem_u32(const void* p) {
    uint32_t a;
    asm("{ .reg .u64 t; cvta.to.shared.u64 t, %1; cvt.u32.u64 %0, t; }" : "=r"(a) : "l"(p));
    return a;
}
__device__ __forceinline__ void ldm4(uint32_t* r, uint32_t addr) {
    asm volatile("ldmatrix.sync.aligned.m8n8.x4.shared.b16 {%0,%1,%2,%3}, [%4];"
                 : "=r"(r[0]), "=r"(r[1]), "=r"(r[2]), "=r"(r[3]) : "r"(addr));
}
__device__ __forceinline__ void ldm4t(uint32_t* r, uint32_t addr) {
    asm volatile("ldmatrix.sync.aligned.m8n8.x4.trans.shared.b16 {%0,%1,%2,%3}, [%4];"
                 : "=r"(r[0]), "=r"(r[1]), "=r"(r[2]), "=r"(r[3]) : "r"(addr));
}
__device__ __forceinline__ void mma16(float* c, const uint32_t* a, const uint32_t* b) {
    asm volatile("mma.sync.aligned.m16n8k16.row.col.f32.f16.f16.f32 "
        "{%0,%1,%2,%3},{%4,%5,%6,%7},{%8,%9},{%0,%1,%2,%3};"
        : "+f"(c[0]), "+f"(c[1]), "+f"(c[2]), "+f"(c[3])
        : "r"(a[0]), "r"(a[1]), "r"(a[2]), "r"(a[3]), "r"(b[0]), "r"(b[1]));
}
#define CPA16(dst, src) \
    asm volatile("cp.async.cg.shared.global [%0], [%1], 16;" :: "r"(dst), "l"(src) : "memory")

// ============================================================================
// fp16 GEMM: block 128x128, 8 warps (64x32), ktile 32, 3-stage, 1 sync/iter.
// Pipeline: wait -> barrier -> compute(kt) -> issue(kt+2).
// MODE: 0=qkv, 1=dots(split-K=4), 2=O trans-B, 3=out, 4=ksw
// ============================================================================
template<int MODE, int KT>
__global__ __launch_bounds__(256) void g16(const float* __restrict__ auxA,
                                           float* __restrict__ outp) {
    extern __shared__ __half sh[];
    __half* AsB = sh;
    __half* BsB = sh + 3 * STG_H;
    const int t = threadIdx.x, lane = t & 31, warp = t >> 5;
    const int bx = blockIdx.x, by = blockIdx.y;
    const int h = (MODE == 1) ? (blockIdx.z & 7) : blockIdx.z;
    const int split = (MODE == 1) ? (blockIdx.z >> 3) : 0;

    const __half *A, *B; int lda, ldb;
    if (MODE == 0)      { A = g_xh + (size_t)by * 128 * 128; lda = 128;
                          B = g_wt + (size_t)bx * 128 * 128; ldb = 128; }
    else if (MODE == 4) { A = g_xh + (size_t)by * 128 * 128; lda = 128;
                          B = g_wt + (size_t)768 * 128;      ldb = 128; }
    else if (MODE == 1) { A = g_qh + ((size_t)h * 512 + by * 128) * 4096 + split * 1024; lda = 4096;
                          B = g_kh + ((size_t)h * 512 + bx * 128) * 4096 + split * 1024; ldb = 4096; }
    else if (MODE == 2) { A = g_ph + ((size_t)h * 512 + by * 128) * 512; lda = 512;
                          B = g_vh + (size_t)h * 512 * 4096 + bx * 128;  ldb = 4096; }
    else                { A = g_o2 + (size_t)by * 128 * 256; lda = 256;
                          B = g_woutt;                       ldb = 256; }

    auto cpst = [&](int st, int k0) {
        uint32_t da = smem_u32(AsB + st * STG_H), db = smem_u32(BsB + st * STG_H);
#pragma unroll
        for (int c = t; c < 512; c += 256) {
            int row = c >> 2, col = c & 3;
            CPA16(da + row * 80 + col * 16, A + (size_t)row * lda + k0 + col * 8);
        }
        if (MODE == 2) {
#pragma unroll
            for (int c = t; c < 512; c += 256) {
                int row = c >> 4, col = c & 15;
                CPA16(db + row * 272 + col * 16, B + (size_t)(k0 + row) * ldb + col * 8);
            }
        } else {
#pragma unroll
            for (int c = t; c < 512; c += 256) {
                int row = c >> 2, col = c & 3;
                CPA16(db + row * 80 + col * 16, B + (size_t)row * ldb + k0 + col * 8);
            }
        }
        asm volatile("cp.async.commit_group;" ::: "memory");
    };

    float acc[4][4][4] = {};
    const int wm0 = (warp >> 2) * 64, wn0 = (warp & 3) * 32;
    const int q = lane >> 3;

    cpst(0, 0);
    cpst(1, 32);
    int st = 0;
    for (int kt = 0; kt < KT; kt++) {
        if (kt + 1 < KT) asm volatile("cp.async.wait_group 1;" ::: "memory");
        else             asm volatile("cp.async.wait_group 0;" ::: "memory");
        __syncthreads();                      // other threads' copies for stage st visible
        uint32_t ab = smem_u32(AsB + st * STG_H), bb = smem_u32(BsB + st * STG_H);
#pragma unroll
        for (int kk = 0; kk < 32; kk += 16) {
            uint32_t af[4][4], bf[2][4];
#pragma unroll
            for (int mt = 0; mt < 4; mt++)
                ldm4(af[mt], ab + (wm0 + mt * 16 + (lane & 15)) * 80 + (kk + (lane >> 4) * 8) * 2);
#pragma unroll
            for (int np = 0; np < 2; np++) {
                if (MODE == 2)
                    ldm4t(bf[np], bb + (kk + (q & 1) * 8 + (lane & 7)) * 272
                                     + (wn0 + np * 16 + (q >> 1) * 8) * 2);
                else
                    ldm4(bf[np], bb + (wn0 + np * 16 + (q >> 1) * 8 + (lane & 7)) * 80
                                    + (kk + (q & 1) * 8) * 2);
            }
#pragma unroll
            for (int mt = 0; mt < 4; mt++)
#pragma unroll
                for (int nt = 0; nt < 4; nt++)
                    mma16(acc[mt][nt], af[mt], &bf[nt >> 1][(nt & 1) * 2]);
        }
        if (kt + 2 < KT) {
            int ns = st + 2; if (ns >= 3) ns -= 3;   // == (kt-1)%3, safe post-barrier
            cpst(ns, (kt + 2) * 32);
        }
        st = (st == 2) ? 0 : st + 1;
    }

#pragma unroll
    for (int mt = 0; mt < 4; mt++)
#pragma unroll
        for (int nt = 0; nt < 4; nt++)
#pragma unroll
            for (int hf = 0; hf < 2; hf++) {
                int mrow = wm0 + mt * 16 + (lane >> 2) + hf * 8;
                int ncol = wn0 + nt * 8 + (lane & 3) * 2;
                float v0 = acc[mt][nt][hf * 2], v1 = acc[mt][nt][hf * 2 + 1];
                if (MODE == 0) {
                    int m = by * 128 + mrow, c = bx * 128 + ncol;
                    int r = m >> 9, n = m & 511;
                    if (c < 256) {
                        int hh = c >> 5, d = c & 31;
                        float w = g_wrow[(n * 8 + hh) * 128 + r];
                        *reinterpret_cast<__half2*>(
                            &g_qh[((size_t)(hh * 512 + n)) * 4096 + r * 32 + d]) =
                            __floats2half2_rn(v0 * w, v1 * w);
                    } else if (c < 512) {
                        int cc = c - 256, hh = cc >> 5, d = cc & 31;
                        *reinterpret_cast<__half2*>(
                            &g_kh[((size_t)(hh * 512 + n)) * 4096 + r * 32 + d]) =
                            __floats2half2_rn(v0, v1);
                    } else {
                        int cc = c - 512, hh = cc >> 5, d = cc & 31;
                        *reinterpret_cast<__half2*>(
                            &g_vh[((size_t)(hh * 512 + n)) * 4096 + r * 32 + d]) =
                            __floats2half2_rn(v0, v1);
                    }
                } else if (MODE == 4) {
                    int m = by * 128 + mrow;
                    g_ksw[(size_t)m * 128 + ncol]     = v0 + auxA[ncol];
                    g_ksw[(size_t)m * 128 + ncol + 1] = v1 + auxA[ncol + 1];
                } else if (MODE == 1) {
                    int i = by * 128 + mrow, j = bx * 128 + ncol;
                    size_t off = (size_t)split * DPL + ((size_t)h * 512 + i) * 512 + j;
                    g_dots[off]     = v0;
                    g_dots[off + 1] = v1;
                } else if (MODE == 2) {
                    int i = by * 128 + mrow, tcol = bx * 128 + ncol;
                    int r = tcol >> 5, d = tcol & 31;
                    *reinterpret_cast<__half2*>(
                        &g_o2[((size_t)r * 512 + i) * 256 + h * 32 + d]) =
                        __floats2half2_rn(v0, v1);
                } else {
                    int m = by * 128 + mrow;
                    outp[(size_t)m * 128 + ncol]     = v0 + auxA[ncol];
                    outp[(size_t)m * 128 + ncol + 1] = v1 + auxA[ncol + 1];
                }
            }
}

// ============================================================================
__global__ void conv_x(const float* __restrict__ x) {
    size_t i = ((size_t)blockIdx.x * 256 + threadIdx.x) * 4;
    float4 v = *reinterpret_cast<const float4*>(x + i);
    __half2* d = reinterpret_cast<__half2*>(&g_xh[i]);
    d[0] = __floats2half2_rn(v.x, v.y);
    d[1] = __floats2half2_rn(v.z, v.w);
}

__global__ void conv_w(const float* __restrict__ Wq, const float* __restrict__ Wkv,
                       const float* __restrict__ Wk_sw, const float* __restrict__ Wout) {
    int g = blockIdx.x * 256 + threadIdx.x;
    if (g < 114688) {
        int row = g >> 7, k = g & 127;
        float v;
        if (row < 256)      v = Wq[k * 256 + row];
        else if (row < 768) v = Wkv[k * 512 + (row - 256)];
        else                v = Wk_sw[k * 128 + (row - 768)];
        g_wt[g] = __float2half_rn(v);
    } else {
        int g2 = g - 114688;
        int c = g2 >> 8, k = g2 & 255;
        g_woutt[g2] = __float2half_rn(Wout[k * 128 + c]);
    }
}

__global__ void qsw_kernel(const float* __restrict__ x, const float* __restrict__ Wq_sw,
                           const float* __restrict__ bq_sw) {
    int n = blockIdx.x, c = threadIdx.x;
    __shared__ float xr[128];
    xr[c] = x[(size_t)n * 128 + c];
    __syncthreads();
    float acc = bq_sw[c];
#pragma unroll 8
    for (int k = 0; k < 128; k++) acc += xr[k] * Wq_sw[k * 128 + c];
    g_qsw[n * 128 + c] = acc;
}

__global__ void sw_reduce_kernel() {
    int m = blockIdx.x, r = m >> 9, n = m & 511, c = threadIdx.x;
    float prod = g_ksw[(size_t)m * 128 + c] * g_qsw[n * 128 + c];
#pragma unroll
    for (int o = 8; o; o >>= 1) prod += __shfl_down_sync(0xffffffffu, prod, o, 16);
    if ((c & 15) == 0) g_wrow[(n * 8 + (c >> 4)) * 128 + r] = prod * 0.25f;
}

__global__ void wrow_softmax_kernel() {
    int row = blockIdx.x, t = threadIdx.x;
    float v = g_wrow[(size_t)row * 128 + t];
    __shared__ float sm[128];
    sm[t] = v; __syncthreads();
#pragma unroll
    for (int s = 64; s > 0; s >>= 1) { if (t < s) sm[t] = fmaxf(sm[t], sm[t + s]); __syncthreads(); }
    float mx = sm[0]; __syncthreads();
    float e = expf(v - mx);
    sm[t] = e; __syncthreads();
#pragma unroll
    for (int s = 64; s > 0; s >>= 1) { if (t < s) sm[t] += sm[t + s]; __syncthreads(); }
    g_wrow[(size_t)row * 128 + t] = e / sm[0];
}

__global__ void pbh_kernel(const float* __restrict__ pair_bias, const float* __restrict__ ln_g,
                           const float* __restrict__ ln_b, const float* __restrict__ Wpair) {
    int warp = threadIdx.x >> 5, lane = threadIdx.x & 31;
    int idx = blockIdx.x * 8 + warp;
    int i = idx >> 9, j = idx & 511;
    float4 v = *reinterpret_cast<const float4*>(&pair_bias[(size_t)idx * 128 + lane * 4]);
    float s  = v.x + v.y + v.z + v.w;
    float sq = v.x * v.x + v.y * v.y + v.z * v.z + v.w * v.w;
#pragma unroll
    for (int o = 16; o; o >>= 1) {
        s  += __shfl_xor_sync(0xffffffffu, s, o);
        sq += __shfl_xor_sync(0xffffffffu, sq, o);
    }
    float mean = s * (1.0f / 128.0f);
    float var  = sq * (1.0f / 128.0f) - mean * mean;
    float rstd = rsqrtf(var + 1e-5f);
    float vv[4] = {v.x, v.y, v.z, v.w};
    float ph[8] = {};
#pragma unroll
    for (int e = 0; e < 4; e++) {
        int p = lane * 4 + e;
        float nz = (vv[e] - mean) * rstd * ln_g[p] + ln_b[p];
#pragma unroll
        for (int hh = 0; hh < 8; hh++) ph[hh] += nz * Wpair[p * 8 + hh];
    }
#pragma unroll
    for (int hh = 0; hh < 8; hh++)
#pragma unroll
        for (int o = 16; o; o >>= 1) ph[hh] += __shfl_xor_sync(0xffffffffu, ph[hh], o);
    if (lane == 0)
#pragma unroll
        for (int hh = 0; hh < 8; hh++) g_pbh[(((size_t)hh << 9) + i) * NN + j] = ph[hh];
}

__global__ void attn_softmax_kernel() {
    size_t row = blockIdx.x;
    int t = threadIdx.x;
    size_t off0 = row * 512 + t, off1 = off0 + 256;
    const float scale = 0.17677669529663687f;
    float v0 = (g_dots[off0] + g_dots[off0 + DPL] + g_dots[off0 + 2 * DPL] + g_dots[off0 + 3 * DPL])
               * scale + g_pbh[off0];
    float v1 = (g_dots[off1] + g_dots[off1 + DPL] + g_dots[off1 + 2 * DPL] + g_dots[off1 + 3 * DPL])
               * scale + g_pbh[off1];
    __shared__ float sm[256];
    sm[t] = fmaxf(v0, v1); __syncthreads();
#pragma unroll
    for (int s = 128; s > 0; s >>= 1) { if (t < s) sm[t] = fmaxf(sm[t], sm[t + s]); __syncthreads(); }
    float mx = sm[0]; __syncthreads();
    float e0 = expf(v0 - mx), e1 = expf(v1 - mx);
    sm[t] = e0 + e1; __syncthreads();
#pragma unroll
    for (int s = 128; s > 0; s >>= 1) { if (t < s) sm[t] += sm[t + s]; __syncthreads(); }
    float inv = 1.0f / sm[0];
    g_ph[row * 512 + t]       = __float2half_rn(e0 * inv);
    g_ph[row * 512 + t + 256] = __float2half_rn(e1 * inv);
}

// ============================================================================
extern "C" void kernel_launch(void* const* d_in, const int* in_sizes, int n_in,
                              void* d_out, int out_size) {
    (void)in_sizes; (void)n_in; (void)out_size;
    const float* x         = (const float*)d_in[0];
    const float* pair_bias = (const float*)d_in[1];
    const float* Wq        = (const float*)d_in[2];
    const float* Wkv       = (const float*)d_in[3];
    const float* Wout      = (const float*)d_in[4];
    const float* b_out     = (const float*)d_in[5];
    const float* ln_g      = (const float*)d_in[6];
    const float* ln_b      = (const float*)d_in[7];
    const float* Wpair     = (const float*)d_in[8];
    const float* Wq_sw     = (const float*)d_in[9];
    const float* bq_sw     = (const float*)d_in[10];
    const float* Wk_sw     = (const float*)d_in[11];
    const float* bk_sw     = (const float*)d_in[12];
    float* out = (float*)d_out;

    static int attr_done = 0;
    if (!attr_done) {
        cudaFuncSetAttribute(g16<0, 4>,  cudaFuncAttributeMaxDynamicSharedMemorySize, SMEM_BYTES);
        cudaFuncSetAttribute(g16<1, 32>, cudaFuncAttributeMaxDynamicSharedMemorySize, SMEM_BYTES);
        cudaFuncSetAttribute(g16<2, 16>, cudaFuncAttributeMaxDynamicSharedMemorySize, SMEM_BYTES);
        cudaFuncSetAttribute(g16<3, 8>,  cudaFuncAttributeMaxDynamicSharedMemorySize, SMEM_BYTES);
        cudaFuncSetAttribute(g16<4, 4>,  cudaFuncAttributeMaxDynamicSharedMemorySize, SMEM_BYTES);
        attr_done = 1;
    }

    conv_x             <<<8192, 256>>>(x);
    conv_w             <<<576, 256>>>(Wq, Wkv, Wk_sw, Wout);
    qsw_kernel         <<<NN, 128>>>(x, Wq_sw, bq_sw);
    g16<4, 4>          <<<dim3(1, 512), 256, SMEM_BYTES>>>(bk_sw, nullptr);      // ksw
    sw_reduce_kernel   <<<MRN, 128>>>();
    wrow_softmax_kernel<<<NN * HH, 128>>>();
    g16<0, 4>          <<<dim3(6, 512), 256, SMEM_BYTES>>>(nullptr, nullptr);    // qkv
    pbh_kernel         <<<NN * NN / 8, 256>>>(pair_bias, ln_g, ln_b, Wpair);
    g16<1, 32>         <<<dim3(4, 4, 32), 256, SMEM_BYTES>>>(nullptr, nullptr);  // dots sK=4
    attn_softmax_kernel<<<HH * NN, 256>>>();
    g16<2, 16>         <<<dim3(32, 4, 8), 256, SMEM_BYTES>>>(nullptr, nullptr);  // O
    g16<3, 8>          <<<dim3(1, 512), 256, SMEM_BYTES>>>(b_out, out);          // out
}